// round 7
// baseline (speedup 1.0000x reference)
#include <cuda_runtime.h>
#include <cuda_bf16.h>

#define NN 50000
#define EE 800000
#define DM 128
#define RD 32
#define KIN 160
#define LN_EPS 1e-5f

// ---------------- scratch ----------------------------------------------------
__device__ float g_h[NN * DM];
__device__ float g_h2[NN * DM];
__device__ __nv_bfloat16 g_hb[NN * DM];   // bf16 mirror of current h (gather source)
__device__ float g_aggH[NN * DM];
__device__ float g_aggR[NN * RD];
__device__ float g_inv[NN];
__device__ int   g_deg[NN];
__device__ int   g_off[NN + 1];
__device__ int   g_cur[NN];
__device__ int2  g_csr[EE];        // (src, rel) grouped by dst

// ---------------- CSR build ----------------------------------------------------
__global__ void k_zero_int(int* __restrict__ p, int n) {
    int i = blockIdx.x * blockDim.x + threadIdx.x;
    if (i < n) p[i] = 0;
}

__global__ void k_deg(const int* __restrict__ dst) {
    int i = blockIdx.x * blockDim.x + threadIdx.x;
    if (i < EE) atomicAdd(&g_deg[dst[i]], 1);
}

__global__ __launch_bounds__(1024) void k_scan() {
    __shared__ int warp_sums[32];
    const int CH = (NN + 1023) / 1024;
    int t = threadIdx.x, lane = t & 31, w = t >> 5;
    int base = t * CH;
    int s = 0;
    for (int i = 0; i < CH; i++) {
        int idx = base + i;
        if (idx < NN) s += g_deg[idx];
    }
    int v = s;
    #pragma unroll
    for (int o = 1; o < 32; o <<= 1) {
        int u = __shfl_up_sync(0xffffffffu, v, o);
        if (lane >= o) v += u;
    }
    if (lane == 31) warp_sums[w] = v;
    __syncthreads();
    if (w == 0) {
        int u = warp_sums[lane];
        #pragma unroll
        for (int o = 1; o < 32; o <<= 1) {
            int uu = __shfl_up_sync(0xffffffffu, u, o);
            if (lane >= o) u += uu;
        }
        warp_sums[lane] = u;
    }
    __syncthreads();
    int excl = v - s + (w > 0 ? warp_sums[w - 1] : 0);
    int run = excl;
    for (int i = 0; i < CH; i++) {
        int idx = base + i;
        if (idx < NN) {
            int d = g_deg[idx];
            g_off[idx] = run;
            g_cur[idx] = run;
            g_inv[idx] = d > 0 ? (1.f / (float)d) : 0.f;
            run += d;
        }
    }
    if (t == 0) g_off[NN] = EE;
}

__global__ void k_scatter(const int* __restrict__ src, const int* __restrict__ dst,
                          const int* __restrict__ erel) {
    int i = blockIdx.x * blockDim.x + threadIdx.x;
    if (i < EE) {
        int d = dst[i];
        int pos = atomicAdd(&g_cur[d], 1);
        g_csr[pos] = make_int2(src[i], erel[i]);
    }
}

// ---------------- gather (bf16 h rows): aggH[v]=mean h[src], aggR[v]=mean rel --
__device__ __forceinline__ void acc_bf4(float4& a, uint2 w) {
    __nv_bfloat162 lo = *reinterpret_cast<__nv_bfloat162*>(&w.x);
    __nv_bfloat162 hi = *reinterpret_cast<__nv_bfloat162*>(&w.y);
    float2 flo = __bfloat1622float2(lo);
    float2 fhi = __bfloat1622float2(hi);
    a.x += flo.x; a.y += flo.y; a.z += fhi.x; a.w += fhi.y;
}

__global__ __launch_bounds__(256) void k_gather(
    const float* __restrict__ rel)
{
    __shared__ int2 stage[8][32];
    int w = threadIdx.x >> 5, lane = threadIdx.x & 31;
    int v = blockIdx.x * 8 + w;
    if (v >= NN) return;
    int2* st = stage[w];
    const uint2* hb = (const uint2*)g_hb;   // 4 bf16 per uint2, 32 uint2 per row

    int e = g_off[v], end = g_off[v + 1];
    float4 a0 = make_float4(0.f, 0.f, 0.f, 0.f), a1 = a0, a2 = a0, a3 = a0;
    float r0s = 0.f, r1s = 0.f, r2s = 0.f, r3s = 0.f;

    while (e < end) {
        int n = min(32, end - e);
        if (lane < n) st[lane] = g_csr[e + lane];
        __syncwarp();
        int j = 0;
        for (; j + 4 <= n; j += 4) {
            int2 p0 = st[j], p1 = st[j + 1], p2 = st[j + 2], p3 = st[j + 3];
            uint2 h0 = hb[(size_t)p0.x * 32 + lane];
            uint2 h1 = hb[(size_t)p1.x * 32 + lane];
            uint2 h2 = hb[(size_t)p2.x * 32 + lane];
            uint2 h3 = hb[(size_t)p3.x * 32 + lane];
            float q0 = rel[p0.y * RD + lane];
            float q1 = rel[p1.y * RD + lane];
            float q2 = rel[p2.y * RD + lane];
            float q3 = rel[p3.y * RD + lane];
            acc_bf4(a0, h0); acc_bf4(a1, h1); acc_bf4(a2, h2); acc_bf4(a3, h3);
            r0s += q0; r1s += q1; r2s += q2; r3s += q3;
        }
        for (; j < n; j++) {
            int2 p0 = st[j];
            uint2 h0 = hb[(size_t)p0.x * 32 + lane];
            acc_bf4(a0, h0);
            r0s += rel[p0.y * RD + lane];
        }
        e += n;
        __syncwarp();
    }

    float iv = g_inv[v];
    float4 acc;
    acc.x = (a0.x + a1.x + a2.x + a3.x) * iv;
    acc.y = (a0.y + a1.y + a2.y + a3.y) * iv;
    acc.z = (a0.z + a1.z + a2.z + a3.z) * iv;
    acc.w = (a0.w + a1.w + a2.w + a3.w) * iv;
    ((float4*)(g_aggH + (size_t)v * DM))[lane] = acc;
    g_aggR[v * RD + lane] = (r0s + r1s + r2s + r3s) * iv;
}

// ---------------- packed fp32 GEMM machinery -----------------------------------
extern __shared__ float smdyn[];

#define PFMA(D, A, B) \
    asm("fma.rn.f32x2 %0, %1, %2, %0;" : "+l"(D) : "l"(A), "l"(B));

__device__ __forceinline__ float phsum(unsigned long long v) {
    float lo = __uint_as_float((unsigned)v);
    float hi = __uint_as_float((unsigned)(v >> 32));
    return lo + hi;
}

__device__ __forceinline__ uint2 pack_bf4(float4 o) {
    __nv_bfloat162 lo = __floats2bfloat162_rn(o.x, o.y);
    __nv_bfloat162 hi = __floats2bfloat162_rn(o.z, o.w);
    uint2 r;
    r.x = *reinterpret_cast<unsigned*>(&lo);
    r.y = *reinterpret_cast<unsigned*>(&hi);
    return r;
}

// Conflict-free k-pair weight staging: per k-pair kp a 2*DM region;
// A half (cols%4 in {0,1}) densely 16B/lane, B half (cols%4 in {2,3}) at +DM.
#define STAGE_PAIRS(Wp, W, K)                                              \
    for (int idx = tid; idx < ((K) / 2) * DM; idx += 256) {                \
        int kp  = idx / DM;                                                \
        int col = idx % DM;                                                \
        float w0 = (W)[(2 * kp) * DM + col];                               \
        float w1 = (W)[(2 * kp + 1) * DM + col];                           \
        int dst = kp * 2 * DM + ((col & 2) ? DM : 0)                       \
                + ((col >> 2) << 2) + ((col & 1) << 1);                    \
        (Wp)[dst] = w0; (Wp)[dst + 1] = w1;                                \
    }

#define PROWS(BI, R0, R1, R2, R3)                                                    \
    PFMA(R0, (BI).x, wA0.x) PFMA(R1, (BI).x, wA0.y) PFMA(R2, (BI).x, wB0.x) PFMA(R3, (BI).x, wB0.y) \
    PFMA(R0, (BI).y, wA1.x) PFMA(R1, (BI).y, wA1.y) PFMA(R2, (BI).y, wB1.x) PFMA(R3, (BI).y, wB1.y)

#define SEG8(Wb, OFF, LEN, STR)                                              \
    _Pragma("unroll 4")                                                      \
    for (int k = 0; k < (LEN); k += 4) {                                     \
        ulonglong2 b0 = *(const ulonglong2*)(in + 0 * (STR) + (OFF) + k);    \
        ulonglong2 b1 = *(const ulonglong2*)(in + 1 * (STR) + (OFF) + k);    \
        ulonglong2 b2 = *(const ulonglong2*)(in + 2 * (STR) + (OFF) + k);    \
        ulonglong2 b3 = *(const ulonglong2*)(in + 3 * (STR) + (OFF) + k);    \
        ulonglong2 b4 = *(const ulonglong2*)(in + 4 * (STR) + (OFF) + k);    \
        ulonglong2 b5 = *(const ulonglong2*)(in + 5 * (STR) + (OFF) + k);    \
        ulonglong2 b6 = *(const ulonglong2*)(in + 6 * (STR) + (OFF) + k);    \
        ulonglong2 b7 = *(const ulonglong2*)(in + 7 * (STR) + (OFF) + k);    \
        const float* wb = (Wb) + k * DM + c;                                 \
        ulonglong2 wA0 = *(const ulonglong2*)(wb);                           \
        ulonglong2 wB0 = *(const ulonglong2*)(wb + DM);                      \
        ulonglong2 wA1 = *(const ulonglong2*)(wb + 2 * DM);                  \
        ulonglong2 wB1 = *(const ulonglong2*)(wb + 3 * DM);                  \
        PROWS(b0, A00, A01, A02, A03)                                        \
        PROWS(b1, A10, A11, A12, A13)                                        \
        PROWS(b2, A20, A21, A22, A23)                                        \
        PROWS(b3, A30, A31, A32, A33)                                        \
        PROWS(b4, A40, A41, A42, A43)                                        \
        PROWS(b5, A50, A51, A52, A53)                                        \
        PROWS(b6, A60, A61, A62, A63)                                        \
        PROWS(b7, A70, A71, A72, A73)                                        \
    }

#define DECL_ACC8                                                   \
    unsigned long long A00 = 0, A01 = 0, A02 = 0, A03 = 0,          \
                       A10 = 0, A11 = 0, A12 = 0, A13 = 0,          \
                       A20 = 0, A21 = 0, A22 = 0, A23 = 0,          \
                       A30 = 0, A31 = 0, A32 = 0, A33 = 0,          \
                       A40 = 0, A41 = 0, A42 = 0, A43 = 0,          \
                       A50 = 0, A51 = 0, A52 = 0, A53 = 0,          \
                       A60 = 0, A61 = 0, A62 = 0, A63 = 0,          \
                       A70 = 0, A71 = 0, A72 = 0, A73 = 0;

#define ROWACC(R0, R1, R2, R3) \
    make_float4(phsum(R0) + bb.x, phsum(R1) + bb.y, phsum(R2) + bb.z, phsum(R3) + bb.w)

// ---------------- input projection ----------------------------------------------
__global__ __launch_bounds__(256) void k_input(
    const float* __restrict__ x, const int* __restrict__ label,
    const float* __restrict__ lemb, const float* __restrict__ W,
    const float* __restrict__ b, float* __restrict__ hout)
{
    float* Ws  = smdyn;             // KIN*DM (pair layout)
    float* bs  = Ws + KIN * DM;
    float* ins = bs + DM;           // 8 warps * 8 rows * KIN
    int tid = threadIdx.x;

    STAGE_PAIRS(Ws, W, KIN)
    for (int i = tid; i < DM; i += 256) bs[i] = b[i];
    __syncthreads();

    int w = tid >> 5, lane = tid & 31;
    int c = lane * 4;
    const int ntiles = NN / 8;

    for (int tile = blockIdx.x * 8 + w; tile < ntiles; tile += gridDim.x * 8) {
        int v0 = tile * 8;
        float* in = ins + w * (8 * KIN);
        #pragma unroll
        for (int r = 0; r < 8; r++) {
            int v = v0 + r;
            float* inr = in + r * KIN;
            ((float4*)inr)[lane] = ((const float4*)(x + (size_t)v * DM))[lane];
            int lb = __ldg(&label[v]);
            inr[DM + lane] = lemb[lb * RD + lane];
        }
        __syncwarp();

        DECL_ACC8
        SEG8(Ws, 0, KIN, KIN)

        float4 bb = *(float4*)(bs + c);
        float4 accs[8];
        accs[0] = ROWACC(A00, A01, A02, A03);
        accs[1] = ROWACC(A10, A11, A12, A13);
        accs[2] = ROWACC(A20, A21, A22, A23);
        accs[3] = ROWACC(A30, A31, A32, A33);
        accs[4] = ROWACC(A40, A41, A42, A43);
        accs[5] = ROWACC(A50, A51, A52, A53);
        accs[6] = ROWACC(A60, A61, A62, A63);
        accs[7] = ROWACC(A70, A71, A72, A73);
        #pragma unroll
        for (int r = 0; r < 8; r++) {
            float4 o = accs[r];
            o.x = fmaxf(o.x, 0.f); o.y = fmaxf(o.y, 0.f);
            o.z = fmaxf(o.z, 0.f); o.w = fmaxf(o.w, 0.f);
            ((float4*)(hout + (size_t)(v0 + r) * DM))[lane] = o;
            ((uint2*)g_hb)[(size_t)(v0 + r) * 32 + lane] = pack_bf4(o);
        }
    }
}

// ---------------- node pass: 3-GEMM + bias + relu + layernorm --------------------
__global__ __launch_bounds__(256) void k_node(
    const float* __restrict__ hin,
    const float* __restrict__ Wself, const float* __restrict__ Wn,
    const float* __restrict__ Wr, const float* __restrict__ bias,
    const float* __restrict__ lng, const float* __restrict__ lnb,
    float* __restrict__ hout, int write_bf16)
{
    float* Ws  = smdyn;                 // DM*DM pair layout
    float* Wns = Ws + DM * DM;
    float* Wrs = Wns + DM * DM;         // RD*DM
    float* bs  = Wrs + RD * DM;
    float* gs  = bs + DM;
    float* lbs = gs + DM;
    float* ins = lbs + DM;              // 8 warps * 8 rows * 288

    int tid = threadIdx.x;
    STAGE_PAIRS(Ws,  Wself, DM)
    STAGE_PAIRS(Wns, Wn,    DM)
    STAGE_PAIRS(Wrs, Wr,    RD)
    for (int i = tid; i < DM; i += 256) {
        bs[i] = bias[i]; gs[i] = lng[i]; lbs[i] = lnb[i];
    }
    __syncthreads();

    int w = tid >> 5, lane = tid & 31;
    int c = lane * 4;
    const int ntiles = NN / 8;

    for (int tile = blockIdx.x * 8 + w; tile < ntiles; tile += gridDim.x * 8) {
        int v0 = tile * 8;
        float* in = ins + w * (8 * 288);
        #pragma unroll
        for (int r = 0; r < 8; r++) {
            int v = v0 + r;
            float* inr = in + r * 288;
            ((float4*)inr)[lane]        = ((const float4*)(hin + (size_t)v * DM))[lane];
            ((float4*)(inr + DM))[lane] = ((const float4*)(g_aggH + (size_t)v * DM))[lane];
            inr[2 * DM + lane]          = g_aggR[v * RD + lane];
        }
        __syncwarp();

        DECL_ACC8
        SEG8(Ws,  0,      DM, 288)
        SEG8(Wns, DM,     DM, 288)
        SEG8(Wrs, 2 * DM, RD, 288)

        float4 bb = *(float4*)(bs + c);
        float4 accs[8];
        accs[0] = ROWACC(A00, A01, A02, A03);
        accs[1] = ROWACC(A10, A11, A12, A13);
        accs[2] = ROWACC(A20, A21, A22, A23);
        accs[3] = ROWACC(A30, A31, A32, A33);
        accs[4] = ROWACC(A40, A41, A42, A43);
        accs[5] = ROWACC(A50, A51, A52, A53);
        accs[6] = ROWACC(A60, A61, A62, A63);
        accs[7] = ROWACC(A70, A71, A72, A73);

        #pragma unroll
        for (int r = 0; r < 8; r++) {
            float4 o = accs[r];
            o.x = fmaxf(o.x, 0.f); o.y = fmaxf(o.y, 0.f);
            o.z = fmaxf(o.z, 0.f); o.w = fmaxf(o.w, 0.f);

            float s1 = o.x + o.y + o.z + o.w;
            float s2 = o.x * o.x + o.y * o.y + o.z * o.z + o.w * o.w;
            #pragma unroll
            for (int off = 16; off > 0; off >>= 1) {
                s1 += __shfl_xor_sync(0xffffffffu, s1, off);
                s2 += __shfl_xor_sync(0xffffffffu, s2, off);
            }
            float mu  = s1 * (1.f / 128.f);
            float var = s2 * (1.f / 128.f) - mu * mu;
            float rs  = rsqrtf(var + LN_EPS);

            float4 o4;
            o4.x = (o.x - mu) * rs * gs[c + 0] + lbs[c + 0];
            o4.y = (o.y - mu) * rs * gs[c + 1] + lbs[c + 1];
            o4.z = (o.z - mu) * rs * gs[c + 2] + lbs[c + 2];
            o4.w = (o.w - mu) * rs * gs[c + 3] + lbs[c + 3];
            ((float4*)(hout + (size_t)(v0 + r) * DM))[lane] = o4;
            if (write_bf16)
                ((uint2*)g_hb)[(size_t)(v0 + r) * 32 + lane] = pack_bf4(o4);
        }
    }
}

// ---------------- host launch ------------------------------------------------------
extern "C" void kernel_launch(void* const* d_in, const int* in_sizes, int n_in,
                              void* d_out, int out_size)
{
    const float* x      = (const float*)d_in[0];
    const int*   label  = (const int*)d_in[1];
    const int*   eidx   = (const int*)d_in[2];
    const int*   erel   = (const int*)d_in[3];
    const float* lemb   = (const float*)d_in[4];
    const float* Win    = (const float*)d_in[5];
    const float* bin    = (const float*)d_in[6];
    const float* relemb = (const float*)d_in[7];
    const float* Wn     = (const float*)d_in[8];
    const float* Wself  = (const float*)d_in[9];
    const float* bself  = (const float*)d_in[10];
    const float* Wr     = (const float*)d_in[11];
    const float* lng    = (const float*)d_in[12];
    const float* lnb    = (const float*)d_in[13];
    float* out = (float*)d_out;

    float *p_h, *p_h2;
    int *p_deg;
    cudaGetSymbolAddress((void**)&p_h,   g_h);
    cudaGetSymbolAddress((void**)&p_h2,  g_h2);
    cudaGetSymbolAddress((void**)&p_deg, g_deg);

    const int smemI = (KIN * DM + DM + 8 * 8 * KIN) * sizeof(float);
    const int smemN = (2 * DM * DM + RD * DM + 3 * DM + 8 * 8 * 288) * sizeof(float);
    cudaFuncSetAttribute(k_input, cudaFuncAttributeMaxDynamicSharedMemorySize, smemI);
    cudaFuncSetAttribute(k_node,  cudaFuncAttributeMaxDynamicSharedMemorySize, smemN);

    // CSR build
    k_zero_int<<<(NN + 255) / 256, 256>>>(p_deg, NN);
    k_deg<<<(EE + 255) / 256, 256>>>(eidx + EE);
    k_scan<<<1, 1024>>>();
    k_scatter<<<(EE + 255) / 256, 256>>>(eidx, eidx + EE, erel);

    // input projection (writes fp32 h + bf16 mirror)
    k_input<<<148, 256, smemI>>>(x, label, lemb, Win, bin, p_h);

    const float* hin = p_h;
    for (int l = 0; l < 2; l++) {
        float* hout = (l == 0) ? p_h2 : out;
        k_gather<<<(NN + 7) / 8, 256>>>(relemb + l * 1024 * RD);
        k_node<<<148, 256, smemN>>>(hin,
                                    Wself + l * DM * DM, Wn + l * DM * DM,
                                    Wr + l * RD * DM, bself + l * DM,
                                    lng + l * DM, lnb + l * DM, hout,
                                    (l == 0) ? 1 : 0);
        hin = hout;
    }
}

// round 8
// speedup vs baseline: 1.1701x; 1.1701x over previous
#include <cuda_runtime.h>

#define NN 50000
#define EE 800000
#define DM 128
#define RD 32
#define LN_EPS 1e-5f
#define NTILE ((NN + 127) / 128)   // 391 tiles of 128 nodes

// ---------------- scratch ----------------------------------------------------
__device__ float g_h[NN * DM];
__device__ float g_h2[NN * DM];
__device__ float g_aggH[NN * DM];
__device__ float g_aggR[NN * RD];
__device__ float g_inv[NN];
__device__ int   g_deg[NN];
__device__ int   g_off[NN + 1];
__device__ int   g_cur[NN];
__device__ int2  g_csr[EE];        // (src, rel) grouped by dst

// ---------------- CSR build ----------------------------------------------------
__global__ void k_deg(const int* __restrict__ dst) {
    int i = blockIdx.x * blockDim.x + threadIdx.x;
    if (i < EE) atomicAdd(&g_deg[dst[i]], 1);
}

__global__ __launch_bounds__(1024) void k_scan() {
    __shared__ int warp_sums[32];
    const int CH = (NN + 1023) / 1024;
    int t = threadIdx.x, lane = t & 31, w = t >> 5;
    int base = t * CH;
    int s = 0;
    for (int i = 0; i < CH; i++) {
        int idx = base + i;
        if (idx < NN) s += g_deg[idx];
    }
    int v = s;
    #pragma unroll
    for (int o = 1; o < 32; o <<= 1) {
        int u = __shfl_up_sync(0xffffffffu, v, o);
        if (lane >= o) v += u;
    }
    if (lane == 31) warp_sums[w] = v;
    __syncthreads();
    if (w == 0) {
        int u = warp_sums[lane];
        #pragma unroll
        for (int o = 1; o < 32; o <<= 1) {
            int uu = __shfl_up_sync(0xffffffffu, u, o);
            if (lane >= o) u += uu;
        }
        warp_sums[lane] = u;
    }
    __syncthreads();
    int excl = v - s + (w > 0 ? warp_sums[w - 1] : 0);
    int run = excl;
    for (int i = 0; i < CH; i++) {
        int idx = base + i;
        if (idx < NN) {
            int d = g_deg[idx];
            g_off[idx] = run;
            g_cur[idx] = run;
            g_inv[idx] = d > 0 ? (1.f / (float)d) : 0.f;
            run += d;
        }
    }
    if (t == 0) g_off[NN] = EE;
}

__global__ void k_scatter(const int* __restrict__ src, const int* __restrict__ dst,
                          const int* __restrict__ erel) {
    int i = blockIdx.x * blockDim.x + threadIdx.x;
    if (i < EE) {
        int d = dst[i];
        int pos = atomicAdd(&g_cur[d], 1);
        g_csr[pos] = make_int2(src[i], erel[i]);
    }
}

// ---------------- gather (fp32): aggH[v]=mean h[src], aggR[v]=mean rel ---------
__global__ __launch_bounds__(256) void k_gather(
    const float* __restrict__ hin, const float* __restrict__ rel)
{
    __shared__ int2 stage[8][32];
    int w = threadIdx.x >> 5, lane = threadIdx.x & 31;
    int v = blockIdx.x * 8 + w;
    if (v >= NN) return;
    int2* st = stage[w];

    int e = g_off[v], end = g_off[v + 1];
    float4 a0 = make_float4(0.f, 0.f, 0.f, 0.f), a1 = a0, a2 = a0, a3 = a0;
    float r0s = 0.f, r1s = 0.f, r2s = 0.f, r3s = 0.f;

    while (e < end) {
        int n = min(32, end - e);
        if (lane < n) st[lane] = g_csr[e + lane];
        __syncwarp();
        int j = 0;
        for (; j + 4 <= n; j += 4) {
            int2 p0 = st[j], p1 = st[j + 1], p2 = st[j + 2], p3 = st[j + 3];
            float4 h0 = ((const float4*)(hin + (size_t)p0.x * DM))[lane];
            float4 h1 = ((const float4*)(hin + (size_t)p1.x * DM))[lane];
            float4 h2 = ((const float4*)(hin + (size_t)p2.x * DM))[lane];
            float4 h3 = ((const float4*)(hin + (size_t)p3.x * DM))[lane];
            float q0 = rel[p0.y * RD + lane];
            float q1 = rel[p1.y * RD + lane];
            float q2 = rel[p2.y * RD + lane];
            float q3 = rel[p3.y * RD + lane];
            a0.x += h0.x; a0.y += h0.y; a0.z += h0.z; a0.w += h0.w;
            a1.x += h1.x; a1.y += h1.y; a1.z += h1.z; a1.w += h1.w;
            a2.x += h2.x; a2.y += h2.y; a2.z += h2.z; a2.w += h2.w;
            a3.x += h3.x; a3.y += h3.y; a3.z += h3.z; a3.w += h3.w;
            r0s += q0; r1s += q1; r2s += q2; r3s += q3;
        }
        for (; j < n; j++) {
            int2 p0 = st[j];
            float4 h0 = ((const float4*)(hin + (size_t)p0.x * DM))[lane];
            a0.x += h0.x; a0.y += h0.y; a0.z += h0.z; a0.w += h0.w;
            r0s += rel[p0.y * RD + lane];
        }
        e += n;
        __syncwarp();
    }

    float iv = g_inv[v];
    float4 acc;
    acc.x = (a0.x + a1.x + a2.x + a3.x) * iv;
    acc.y = (a0.y + a1.y + a2.y + a3.y) * iv;
    acc.z = (a0.z + a1.z + a2.z + a3.z) * iv;
    acc.w = (a0.w + a1.w + a2.w + a3.w) * iv;
    ((float4*)(g_aggH + (size_t)v * DM))[lane] = acc;
    g_aggR[v * RD + lane] = (r0s + r1s + r2s + r3s) * iv;
}

// ---------------- tf32 mma machinery -------------------------------------------
extern __shared__ float smdyn[];

__device__ __forceinline__ unsigned f2tf(float f) {
    unsigned r;
    asm("cvt.rna.tf32.f32 %0, %1;" : "=r"(r) : "f"(f));
    return r;
}

// c[CI..CI+3] += A(16x8) * B(8x8); A rows: g=lane>>2 (+8), cols q=lane&3 (+4)
#define MMA_T(CI, A0, A1, A2, A3, BX, BY)                                       \
    asm("mma.sync.aligned.m16n8k8.row.col.f32.tf32.tf32.f32 "                   \
        "{%0,%1,%2,%3},{%4,%5,%6,%7},{%8,%9},{%0,%1,%2,%3};"                    \
        : "+f"(c[(CI)]), "+f"(c[(CI)+1]), "+f"(c[(CI)+2]), "+f"(c[(CI)+3])      \
        : "r"(A0), "r"(A1), "r"(A2), "r"(A3), "r"(BX), "r"(BY));

// inner: 16 n-tiles against one A fragment
#define MMA_ROW16(BP)                                                           \
    _Pragma("unroll")                                                           \
    for (int nt = 0; nt < 16; nt++) {                                           \
        uint2 b = (BP)[nt * 32];                                                \
        MMA_T(nt * 4, a0, a1, a2, a3, b.x, b.y)                                 \
    }

// ---------------- input projection: h = relu([x, lemb[label]] @ W + b) ---------
// K = 160 -> 20 k-steps (16 from x, 4 from label emb)
__global__ __launch_bounds__(256) void k_input(
    const float* __restrict__ x, const int* __restrict__ label,
    const float* __restrict__ lemb, const float* __restrict__ W,
    const float* __restrict__ b, float* __restrict__ hout)
{
    float* bs = smdyn;                       // 128
    uint2* Bp = (uint2*)(bs + DM);           // 20*512 uint2
    float* Cb = (float*)(Bp + 20 * 512);     // 8 warps * 16*132 floats

    int tid = threadIdx.x;
    for (int idx = tid; idx < 20 * 512; idx += 256) {
        int kk = idx >> 9, r = idx & 511;
        int nt = r >> 5, ln = r & 31;
        int qq = ln & 3, gg = ln >> 2;
        int col = nt * 8 + gg;
        int k0 = kk * 8 + qq;
        float w0 = W[k0 * DM + col];
        float w1 = W[(k0 + 4) * DM + col];
        Bp[idx] = make_uint2(f2tf(w0), f2tf(w1));
    }
    for (int i = tid; i < DM; i += 256) bs[i] = b[i];
    __syncthreads();

    int w = tid >> 5, lane = tid & 31, q = lane & 3, g = lane >> 2;
    float* Cw = Cb + w * (16 * 132);
    int cc = lane * 4;
    float4 bb = *(float4*)(bs + cc);
    const uint2* bpl = Bp + lane;

    for (int tb = blockIdx.x; tb < NTILE; tb += gridDim.x) {
        int v0w = tb * 128 + w * 16;
        int va = min(v0w + g, NN - 1);
        int vb = min(v0w + g + 8, NN - 1);
        int la = __ldg(&label[va]);
        int lb = __ldg(&label[vb]);

        float c[64];
        #pragma unroll
        for (int i = 0; i < 64; i++) c[i] = 0.f;

        for (int kk = 0; kk < 16; kk++) {
            unsigned a0 = f2tf(x[(size_t)va * DM + kk * 8 + q]);
            unsigned a2 = f2tf(x[(size_t)va * DM + kk * 8 + q + 4]);
            unsigned a1 = f2tf(x[(size_t)vb * DM + kk * 8 + q]);
            unsigned a3 = f2tf(x[(size_t)vb * DM + kk * 8 + q + 4]);
            const uint2* bp = bpl + kk * 512;
            MMA_ROW16(bp)
        }
        #pragma unroll
        for (int kk = 0; kk < 4; kk++) {
            unsigned a0 = f2tf(lemb[la * RD + kk * 8 + q]);
            unsigned a2 = f2tf(lemb[la * RD + kk * 8 + q + 4]);
            unsigned a1 = f2tf(lemb[lb * RD + kk * 8 + q]);
            unsigned a3 = f2tf(lemb[lb * RD + kk * 8 + q + 4]);
            const uint2* bp = bpl + (kk + 16) * 512;
            MMA_ROW16(bp)
        }

        #pragma unroll
        for (int nt = 0; nt < 16; nt++) {
            *(float2*)(Cw + g * 132 + nt * 8 + 2 * q)       = make_float2(c[nt*4],   c[nt*4+1]);
            *(float2*)(Cw + (g + 8) * 132 + nt * 8 + 2 * q) = make_float2(c[nt*4+2], c[nt*4+3]);
        }
        __syncwarp();

        for (int r = 0; r < 16; r++) {
            int v = v0w + r;
            if (v >= NN) break;
            float4 o = *(float4*)(Cw + r * 132 + cc);
            o.x = fmaxf(o.x + bb.x, 0.f); o.y = fmaxf(o.y + bb.y, 0.f);
            o.z = fmaxf(o.z + bb.z, 0.f); o.w = fmaxf(o.w + bb.w, 0.f);
            ((float4*)(hout + (size_t)v * DM))[lane] = o;
        }
        __syncwarp();
    }
}

// ---------------- node pass: tf32 mma 3-GEMM + bias + relu + layernorm ---------
// K = 288 -> 36 k-steps (16 from h, 16 from aggH, 4 from aggR)
__global__ __launch_bounds__(256) void k_node(
    const float* __restrict__ hin,
    const float* __restrict__ Wself, const float* __restrict__ Wn,
    const float* __restrict__ Wr, const float* __restrict__ bias,
    const float* __restrict__ lng, const float* __restrict__ lnb,
    float* __restrict__ hout)
{
    float* bs  = smdyn;                      // 128
    float* gs  = bs + DM;                    // 128
    float* lbs = gs + DM;                    // 128
    uint2* Bp  = (uint2*)(lbs + DM);         // 36*512 uint2
    float* Cb  = (float*)(Bp + 36 * 512);    // 8 * 16*132 floats

    int tid = threadIdx.x;
    for (int idx = tid; idx < 36 * 512; idx += 256) {
        int kk = idx >> 9, r = idx & 511;
        int nt = r >> 5, ln = r & 31;
        int qq = ln & 3, gg = ln >> 2;
        int col = nt * 8 + gg;
        int k0 = kk * 8 + qq;
        float w0, w1;
        if (k0 < 128)      { w0 = Wself[k0 * DM + col];        w1 = Wself[(k0 + 4) * DM + col]; }
        else if (k0 < 256) { w0 = Wn[(k0 - 128) * DM + col];   w1 = Wn[(k0 - 124) * DM + col]; }
        else               { w0 = Wr[(k0 - 256) * DM + col];   w1 = Wr[(k0 - 252) * DM + col]; }
        Bp[idx] = make_uint2(f2tf(w0), f2tf(w1));
    }
    for (int i = tid; i < DM; i += 256) {
        bs[i] = bias[i]; gs[i] = lng[i]; lbs[i] = lnb[i];
    }
    __syncthreads();

    int w = tid >> 5, lane = tid & 31, q = lane & 3, g = lane >> 2;
    float* Cw = Cb + w * (16 * 132);
    int cc = lane * 4;
    float4 bb = *(float4*)(bs + cc);
    const uint2* bpl = Bp + lane;

    for (int tb = blockIdx.x; tb < NTILE; tb += gridDim.x) {
        int v0w = tb * 128 + w * 16;
        int va = min(v0w + g, NN - 1);
        int vb = min(v0w + g + 8, NN - 1);

        float c[64];
        #pragma unroll
        for (int i = 0; i < 64; i++) c[i] = 0.f;

        for (int kk = 0; kk < 16; kk++) {
            unsigned a0 = f2tf(hin[(size_t)va * DM + kk * 8 + q]);
            unsigned a2 = f2tf(hin[(size_t)va * DM + kk * 8 + q + 4]);
            unsigned a1 = f2tf(hin[(size_t)vb * DM + kk * 8 + q]);
            unsigned a3 = f2tf(hin[(size_t)vb * DM + kk * 8 + q + 4]);
            const uint2* bp = bpl + kk * 512;
            MMA_ROW16(bp)
        }
        for (int kk = 0; kk < 16; kk++) {
            unsigned a0 = f2tf(g_aggH[(size_t)va * DM + kk * 8 + q]);
            unsigned a2 = f2tf(g_aggH[(size_t)va * DM + kk * 8 + q + 4]);
            unsigned a1 = f2tf(g_aggH[(size_t)vb * DM + kk * 8 + q]);
            unsigned a3 = f2tf(g_aggH[(size_t)vb * DM + kk * 8 + q + 4]);
            const uint2* bp = bpl + (kk + 16) * 512;
            MMA_ROW16(bp)
        }
        #pragma unroll
        for (int kk = 0; kk < 4; kk++) {
            unsigned a0 = f2tf(g_aggR[(size_t)va * RD + kk * 8 + q]);
            unsigned a2 = f2tf(g_aggR[(size_t)va * RD + kk * 8 + q + 4]);
            unsigned a1 = f2tf(g_aggR[(size_t)vb * RD + kk * 8 + q]);
            unsigned a3 = f2tf(g_aggR[(size_t)vb * RD + kk * 8 + q + 4]);
            const uint2* bp = bpl + (kk + 32) * 512;
            MMA_ROW16(bp)
        }

        #pragma unroll
        for (int nt = 0; nt < 16; nt++) {
            *(float2*)(Cw + g * 132 + nt * 8 + 2 * q)       = make_float2(c[nt*4],   c[nt*4+1]);
            *(float2*)(Cw + (g + 8) * 132 + nt * 8 + 2 * q) = make_float2(c[nt*4+2], c[nt*4+3]);
        }
        __syncwarp();

        for (int r = 0; r < 16; r++) {
            int v = v0w + r;
            if (v >= NN) break;
            float4 o = *(float4*)(Cw + r * 132 + cc);
            o.x = fmaxf(o.x + bb.x, 0.f); o.y = fmaxf(o.y + bb.y, 0.f);
            o.z = fmaxf(o.z + bb.z, 0.f); o.w = fmaxf(o.w + bb.w, 0.f);

            float s1 = o.x + o.y + o.z + o.w;
            float s2 = o.x * o.x + o.y * o.y + o.z * o.z + o.w * o.w;
            #pragma unroll
            for (int off = 16; off > 0; off >>= 1) {
                s1 += __shfl_xor_sync(0xffffffffu, s1, off);
                s2 += __shfl_xor_sync(0xffffffffu, s2, off);
            }
            float mu  = s1 * (1.f / 128.f);
            float var = s2 * (1.f / 128.f) - mu * mu;
            float rs  = rsqrtf(var + LN_EPS);

            float4 o4;
            o4.x = (o.x - mu) * rs * gs[cc + 0] + lbs[cc + 0];
            o4.y = (o.y - mu) * rs * gs[cc + 1] + lbs[cc + 1];
            o4.z = (o.z - mu) * rs * gs[cc + 2] + lbs[cc + 2];
            o4.w = (o.w - mu) * rs * gs[cc + 3] + lbs[cc + 3];
            ((float4*)(hout + (size_t)v * DM))[lane] = o4;
        }
        __syncwarp();
    }
}

// ---------------- host launch ------------------------------------------------------
extern "C" void kernel_launch(void* const* d_in, const int* in_sizes, int n_in,
                              void* d_out, int out_size)
{
    const float* x      = (const float*)d_in[0];
    const int*   label  = (const int*)d_in[1];
    const int*   eidx   = (const int*)d_in[2];
    const int*   erel   = (const int*)d_in[3];
    const float* lemb   = (const float*)d_in[4];
    const float* Win    = (const float*)d_in[5];
    const float* bin    = (const float*)d_in[6];
    const float* relemb = (const float*)d_in[7];
    const float* Wn     = (const float*)d_in[8];
    const float* Wself  = (const float*)d_in[9];
    const float* bself  = (const float*)d_in[10];
    const float* Wr     = (const float*)d_in[11];
    const float* lng    = (const float*)d_in[12];
    const float* lnb    = (const float*)d_in[13];
    float* out = (float*)d_out;

    float *p_h, *p_h2;
    int *p_deg;
    cudaGetSymbolAddress((void**)&p_h,   g_h);
    cudaGetSymbolAddress((void**)&p_h2,  g_h2);
    cudaGetSymbolAddress((void**)&p_deg, g_deg);

    // bytes: bias(512) + Bp(20*512*8) + Cbuf(8*16*132*4)
    const int smemI = 512 + 20 * 512 * 8 + 8 * 16 * 132 * 4;          // 150016
    // bytes: bias/ln(1536) + Bp(36*512*8) + Cbuf(67584)
    const int smemN = 1536 + 36 * 512 * 8 + 8 * 16 * 132 * 4;         // 216576
    cudaFuncSetAttribute(k_input, cudaFuncAttributeMaxDynamicSharedMemorySize, smemI);
    cudaFuncSetAttribute(k_node,  cudaFuncAttributeMaxDynamicSharedMemorySize, smemN);

    // CSR build (deg zeroed via memset to keep kernel-launch count low)
    cudaMemsetAsync(p_deg, 0, NN * sizeof(int));
    k_deg<<<(EE + 255) / 256, 256>>>(eidx + EE);
    k_scan<<<1, 1024>>>();
    k_scatter<<<(EE + 255) / 256, 256>>>(eidx, eidx + EE, erel);

    // input projection (tf32 mma)
    k_input<<<148, 256, smemI>>>(x, label, lemb, Win, bin, p_h);

    const float* hin = p_h;
    for (int l = 0; l < 2; l++) {
        float* hout = (l == 0) ? p_h2 : out;
        k_gather<<<(NN + 7) / 8, 256>>>(hin, relemb + l * 1024 * RD);
        k_node<<<148, 256, smemN>>>(hin,
                                    Wself + l * DM * DM, Wn + l * DM * DM,
                                    Wr + l * RD * DM, bself + l * DM,
                                    lng + l * DM, lnb + l * DM, hout);
        hin = hout;
    }
}

// round 9
// speedup vs baseline: 1.3065x; 1.1166x over previous
#include <cuda_runtime.h>

#define NN 50000
#define EE 800000
#define DM 128
#define RD 32
#define LN_EPS 1e-5f
#define NTILE ((NN + 127) / 128)   // 391 tiles of 128 nodes

// ---------------- scratch ----------------------------------------------------
__device__ float g_h[NN * DM];
__device__ float g_h2[NN * DM];
__device__ float g_aggH[NN * DM];
__device__ float g_aggR[NN * RD];
__device__ float g_inv[NN];
__device__ int   g_deg[NN];
__device__ int   g_off[NN + 1];
__device__ int   g_cur[NN];
__device__ int2  g_csr[EE];        // (src, rel) grouped by dst

// ---------------- CSR build ----------------------------------------------------
__global__ void k_deg(const int* __restrict__ dst) {
    int i = blockIdx.x * blockDim.x + threadIdx.x;
    if (i < EE) atomicAdd(&g_deg[dst[i]], 1);
}

// single block, 1024 threads, COALESCED: 49 rounds of 1024 consecutive elements
__global__ __launch_bounds__(1024) void k_scan() {
    __shared__ int wsum[32];
    __shared__ int sh_carry;
    int t = threadIdx.x, lane = t & 31, w = t >> 5;
    if (t == 0) sh_carry = 0;
    __syncthreads();

    for (int base = 0; base < NN; base += 1024) {
        int idx = base + t;
        int d = (idx < NN) ? g_deg[idx] : 0;
        int carry = sh_carry;

        int incl = d;
        #pragma unroll
        for (int o = 1; o < 32; o <<= 1) {
            int u = __shfl_up_sync(0xffffffffu, incl, o);
            if (lane >= o) incl += u;
        }
        if (lane == 31) wsum[w] = incl;
        __syncthreads();
        if (w == 0) {
            int u = wsum[lane];
            #pragma unroll
            for (int o = 1; o < 32; o <<= 1) {
                int uu = __shfl_up_sync(0xffffffffu, u, o);
                if (lane >= o) u += uu;
            }
            wsum[lane] = u;
        }
        __syncthreads();

        int excl = carry + (w > 0 ? wsum[w - 1] : 0) + incl - d;
        if (idx < NN) {
            g_off[idx] = excl;
            g_cur[idx] = excl;
            g_inv[idx] = d > 0 ? (1.f / (float)d) : 0.f;
        }
        int total = wsum[31];
        __syncthreads();
        if (t == 0) sh_carry = carry + total;
        __syncthreads();
    }
    if (t == 0) g_off[NN] = EE;
}

__global__ void k_scatter(const int* __restrict__ src, const int* __restrict__ dst,
                          const int* __restrict__ erel) {
    int i = blockIdx.x * blockDim.x + threadIdx.x;
    if (i < EE) {
        int d = dst[i];
        int pos = atomicAdd(&g_cur[d], 1);
        g_csr[pos] = make_int2(src[i], erel[i]);
    }
}

// ---------------- gather (fp32): aggH[v]=mean h[src], aggR[v]=mean rel ---------
__global__ __launch_bounds__(256) void k_gather(
    const float* __restrict__ hin, const float* __restrict__ rel)
{
    __shared__ int2 stage[8][32];
    int w = threadIdx.x >> 5, lane = threadIdx.x & 31;
    int v = blockIdx.x * 8 + w;
    if (v >= NN) return;
    int2* st = stage[w];

    int e = g_off[v], end = g_off[v + 1];
    float4 a0 = make_float4(0.f, 0.f, 0.f, 0.f), a1 = a0, a2 = a0, a3 = a0;
    float r0s = 0.f, r1s = 0.f, r2s = 0.f, r3s = 0.f;

    while (e < end) {
        int n = min(32, end - e);
        if (lane < n) st[lane] = g_csr[e + lane];
        __syncwarp();
        int j = 0;
        for (; j + 4 <= n; j += 4) {
            int2 p0 = st[j], p1 = st[j + 1], p2 = st[j + 2], p3 = st[j + 3];
            float4 h0 = ((const float4*)(hin + (size_t)p0.x * DM))[lane];
            float4 h1 = ((const float4*)(hin + (size_t)p1.x * DM))[lane];
            float4 h2 = ((const float4*)(hin + (size_t)p2.x * DM))[lane];
            float4 h3 = ((const float4*)(hin + (size_t)p3.x * DM))[lane];
            float q0 = rel[p0.y * RD + lane];
            float q1 = rel[p1.y * RD + lane];
            float q2 = rel[p2.y * RD + lane];
            float q3 = rel[p3.y * RD + lane];
            a0.x += h0.x; a0.y += h0.y; a0.z += h0.z; a0.w += h0.w;
            a1.x += h1.x; a1.y += h1.y; a1.z += h1.z; a1.w += h1.w;
            a2.x += h2.x; a2.y += h2.y; a2.z += h2.z; a2.w += h2.w;
            a3.x += h3.x; a3.y += h3.y; a3.z += h3.z; a3.w += h3.w;
            r0s += q0; r1s += q1; r2s += q2; r3s += q3;
        }
        for (; j < n; j++) {
            int2 p0 = st[j];
            float4 h0 = ((const float4*)(hin + (size_t)p0.x * DM))[lane];
            a0.x += h0.x; a0.y += h0.y; a0.z += h0.z; a0.w += h0.w;
            r0s += rel[p0.y * RD + lane];
        }
        e += n;
        __syncwarp();
    }

    float iv = g_inv[v];
    float4 acc;
    acc.x = (a0.x + a1.x + a2.x + a3.x) * iv;
    acc.y = (a0.y + a1.y + a2.y + a3.y) * iv;
    acc.z = (a0.z + a1.z + a2.z + a3.z) * iv;
    acc.w = (a0.w + a1.w + a2.w + a3.w) * iv;
    ((float4*)(g_aggH + (size_t)v * DM))[lane] = acc;
    g_aggR[v * RD + lane] = (r0s + r1s + r2s + r3s) * iv;
}

// ---------------- tf32 mma machinery -------------------------------------------
extern __shared__ float smdyn[];

__device__ __forceinline__ unsigned f2tf(float f) {
    unsigned r;
    asm("cvt.rna.tf32.f32 %0, %1;" : "=r"(r) : "f"(f));
    return r;
}

#define MMA_T(CI, A0, A1, A2, A3, BX, BY)                                       \
    asm("mma.sync.aligned.m16n8k8.row.col.f32.tf32.tf32.f32 "                   \
        "{%0,%1,%2,%3},{%4,%5,%6,%7},{%8,%9},{%0,%1,%2,%3};"                    \
        : "+f"(c[(CI)]), "+f"(c[(CI)+1]), "+f"(c[(CI)+2]), "+f"(c[(CI)+3])      \
        : "r"(A0), "r"(A1), "r"(A2), "r"(A3), "r"(BX), "r"(BY));

#define MMA_ROW16(BP)                                                           \
    _Pragma("unroll")                                                           \
    for (int nt = 0; nt < 16; nt++) {                                           \
        uint2 b = (BP)[nt * 32];                                                \
        MMA_T(nt * 4, a0, a1, a2, a3, b.x, b.y)                                 \
    }

// ---------------- input projection: h = relu([x, lemb[label]] @ W + b) ---------
__global__ __launch_bounds__(256) void k_input(
    const float* __restrict__ x, const int* __restrict__ label,
    const float* __restrict__ lemb, const float* __restrict__ W,
    const float* __restrict__ b, float* __restrict__ hout)
{
    float* bs = smdyn;                       // 128
    uint2* Bp = (uint2*)(bs + DM);           // 20*512 uint2
    float* Cb = (float*)(Bp + 20 * 512);     // 8 warps * 16*132 floats

    int tid = threadIdx.x;
    for (int idx = tid; idx < 20 * 512; idx += 256) {
        int kk = idx >> 9, r = idx & 511;
        int nt = r >> 5, ln = r & 31;
        int qq = ln & 3, gg = ln >> 2;
        int col = nt * 8 + gg;
        int k0 = kk * 8 + qq;
        float w0 = W[k0 * DM + col];
        float w1 = W[(k0 + 4) * DM + col];
        Bp[idx] = make_uint2(f2tf(w0), f2tf(w1));
    }
    for (int i = tid; i < DM; i += 256) bs[i] = b[i];
    __syncthreads();

    int w = tid >> 5, lane = tid & 31, q = lane & 3, g = lane >> 2;
    float* Cw = Cb + w * (16 * 132);
    int cc = lane * 4;
    float4 bb = *(float4*)(bs + cc);
    const uint2* bpl = Bp + lane;

    for (int tb = blockIdx.x; tb < NTILE; tb += gridDim.x) {
        int v0w = tb * 128 + w * 16;
        int va = min(v0w + g, NN - 1);
        int vb = min(v0w + g + 8, NN - 1);
        int la = __ldg(&label[va]);
        int lb = __ldg(&label[vb]);

        float c[64];
        #pragma unroll
        for (int i = 0; i < 64; i++) c[i] = 0.f;

        #pragma unroll 4
        for (int kk = 0; kk < 16; kk++) {
            unsigned a0 = f2tf(x[(size_t)va * DM + kk * 8 + q]);
            unsigned a2 = f2tf(x[(size_t)va * DM + kk * 8 + q + 4]);
            unsigned a1 = f2tf(x[(size_t)vb * DM + kk * 8 + q]);
            unsigned a3 = f2tf(x[(size_t)vb * DM + kk * 8 + q + 4]);
            const uint2* bp = bpl + kk * 512;
            MMA_ROW16(bp)
        }
        #pragma unroll
        for (int kk = 0; kk < 4; kk++) {
            unsigned a0 = f2tf(lemb[la * RD + kk * 8 + q]);
            unsigned a2 = f2tf(lemb[la * RD + kk * 8 + q + 4]);
            unsigned a1 = f2tf(lemb[lb * RD + kk * 8 + q]);
            unsigned a3 = f2tf(lemb[lb * RD + kk * 8 + q + 4]);
            const uint2* bp = bpl + (kk + 16) * 512;
            MMA_ROW16(bp)
        }

        #pragma unroll
        for (int nt = 0; nt < 16; nt++) {
            *(float2*)(Cw + g * 132 + nt * 8 + 2 * q)       = make_float2(c[nt*4],   c[nt*4+1]);
            *(float2*)(Cw + (g + 8) * 132 + nt * 8 + 2 * q) = make_float2(c[nt*4+2], c[nt*4+3]);
        }
        __syncwarp();

        for (int r = 0; r < 16; r++) {
            int v = v0w + r;
            if (v >= NN) break;
            float4 o = *(float4*)(Cw + r * 132 + cc);
            o.x = fmaxf(o.x + bb.x, 0.f); o.y = fmaxf(o.y + bb.y, 0.f);
            o.z = fmaxf(o.z + bb.z, 0.f); o.w = fmaxf(o.w + bb.w, 0.f);
            ((float4*)(hout + (size_t)v * DM))[lane] = o;
        }
        __syncwarp();
    }
}

// ---------------- node pass: tf32 mma 3-GEMM + bias + relu + layernorm ---------
__global__ __launch_bounds__(256) void k_node(
    const float* __restrict__ hin,
    const float* __restrict__ Wself, const float* __restrict__ Wn,
    const float* __restrict__ Wr, const float* __restrict__ bias,
    const float* __restrict__ lng, const float* __restrict__ lnb,
    float* __restrict__ hout)
{
    float* bs  = smdyn;                      // 128
    float* gs  = bs + DM;                    // 128
    float* lbs = gs + DM;                    // 128
    uint2* Bp  = (uint2*)(lbs + DM);         // 36*512 uint2
    float* Cb  = (float*)(Bp + 36 * 512);    // 8 * 16*132 floats

    int tid = threadIdx.x;
    for (int idx = tid; idx < 36 * 512; idx += 256) {
        int kk = idx >> 9, r = idx & 511;
        int nt = r >> 5, ln = r & 31;
        int qq = ln & 3, gg = ln >> 2;
        int col = nt * 8 + gg;
        int k0 = kk * 8 + qq;
        float w0, w1;
        if (k0 < 128)      { w0 = Wself[k0 * DM + col];        w1 = Wself[(k0 + 4) * DM + col]; }
        else if (k0 < 256) { w0 = Wn[(k0 - 128) * DM + col];   w1 = Wn[(k0 - 124) * DM + col]; }
        else               { w0 = Wr[(k0 - 256) * DM + col];   w1 = Wr[(k0 - 252) * DM + col]; }
        Bp[idx] = make_uint2(f2tf(w0), f2tf(w1));
    }
    for (int i = tid; i < DM; i += 256) {
        bs[i] = bias[i]; gs[i] = lng[i]; lbs[i] = lnb[i];
    }
    __syncthreads();

    int w = tid >> 5, lane = tid & 31, q = lane & 3, g = lane >> 2;
    float* Cw = Cb + w * (16 * 132);
    int cc = lane * 4;
    float4 bb = *(float4*)(bs + cc);
    const uint2* bpl = Bp + lane;

    for (int tb = blockIdx.x; tb < NTILE; tb += gridDim.x) {
        int v0w = tb * 128 + w * 16;
        int va = min(v0w + g, NN - 1);
        int vb = min(v0w + g + 8, NN - 1);

        float c[64];
        #pragma unroll
        for (int i = 0; i < 64; i++) c[i] = 0.f;

        #pragma unroll 4
        for (int kk = 0; kk < 16; kk++) {
            unsigned a0 = f2tf(hin[(size_t)va * DM + kk * 8 + q]);
            unsigned a2 = f2tf(hin[(size_t)va * DM + kk * 8 + q + 4]);
            unsigned a1 = f2tf(hin[(size_t)vb * DM + kk * 8 + q]);
            unsigned a3 = f2tf(hin[(size_t)vb * DM + kk * 8 + q + 4]);
            const uint2* bp = bpl + kk * 512;
            MMA_ROW16(bp)
        }
        #pragma unroll 4
        for (int kk = 0; kk < 16; kk++) {
            unsigned a0 = f2tf(g_aggH[(size_t)va * DM + kk * 8 + q]);
            unsigned a2 = f2tf(g_aggH[(size_t)va * DM + kk * 8 + q + 4]);
            unsigned a1 = f2tf(g_aggH[(size_t)vb * DM + kk * 8 + q]);
            unsigned a3 = f2tf(g_aggH[(size_t)vb * DM + kk * 8 + q + 4]);
            const uint2* bp = bpl + (kk + 16) * 512;
            MMA_ROW16(bp)
        }
        #pragma unroll
        for (int kk = 0; kk < 4; kk++) {
            unsigned a0 = f2tf(g_aggR[(size_t)va * RD + kk * 8 + q]);
            unsigned a2 = f2tf(g_aggR[(size_t)va * RD + kk * 8 + q + 4]);
            unsigned a1 = f2tf(g_aggR[(size_t)vb * RD + kk * 8 + q]);
            unsigned a3 = f2tf(g_aggR[(size_t)vb * RD + kk * 8 + q + 4]);
            const uint2* bp = bpl + (kk + 32) * 512;
            MMA_ROW16(bp)
        }

        #pragma unroll
        for (int nt = 0; nt < 16; nt++) {
            *(float2*)(Cw + g * 132 + nt * 8 + 2 * q)       = make_float2(c[nt*4],   c[nt*4+1]);
            *(float2*)(Cw + (g + 8) * 132 + nt * 8 + 2 * q) = make_float2(c[nt*4+2], c[nt*4+3]);
        }
        __syncwarp();

        for (int r = 0; r < 16; r++) {
            int v = v0w + r;
            if (v >= NN) break;
            float4 o = *(float4*)(Cw + r * 132 + cc);
            o.x = fmaxf(o.x + bb.x, 0.f); o.y = fmaxf(o.y + bb.y, 0.f);
            o.z = fmaxf(o.z + bb.z, 0.f); o.w = fmaxf(o.w + bb.w, 0.f);

            float s1 = o.x + o.y + o.z + o.w;
            float s2 = o.x * o.x + o.y * o.y + o.z * o.z + o.w * o.w;
            #pragma unroll
            for (int off = 16; off > 0; off >>= 1) {
                s1 += __shfl_xor_sync(0xffffffffu, s1, off);
                s2 += __shfl_xor_sync(0xffffffffu, s2, off);
            }
            float mu  = s1 * (1.f / 128.f);
            float var = s2 * (1.f / 128.f) - mu * mu;
            float rs  = rsqrtf(var + LN_EPS);

            float4 o4;
            o4.x = (o.x - mu) * rs * gs[cc + 0] + lbs[cc + 0];
            o4.y = (o.y - mu) * rs * gs[cc + 1] + lbs[cc + 1];
            o4.z = (o.z - mu) * rs * gs[cc + 2] + lbs[cc + 2];
            o4.w = (o.w - mu) * rs * gs[cc + 3] + lbs[cc + 3];
            ((float4*)(hout + (size_t)v * DM))[lane] = o4;
        }
        __syncwarp();
    }
}

// ---------------- host launch ------------------------------------------------------
extern "C" void kernel_launch(void* const* d_in, const int* in_sizes, int n_in,
                              void* d_out, int out_size)
{
    const float* x      = (const float*)d_in[0];
    const int*   label  = (const int*)d_in[1];
    const int*   eidx   = (const int*)d_in[2];
    const int*   erel   = (const int*)d_in[3];
    const float* lemb   = (const float*)d_in[4];
    const float* Win    = (const float*)d_in[5];
    const float* bin    = (const float*)d_in[6];
    const float* relemb = (const float*)d_in[7];
    const float* Wn     = (const float*)d_in[8];
    const float* Wself  = (const float*)d_in[9];
    const float* bself  = (const float*)d_in[10];
    const float* Wr     = (const float*)d_in[11];
    const float* lng    = (const float*)d_in[12];
    const float* lnb    = (const float*)d_in[13];
    float* out = (float*)d_out;

    float *p_h, *p_h2;
    int *p_deg;
    cudaGetSymbolAddress((void**)&p_h,   g_h);
    cudaGetSymbolAddress((void**)&p_h2,  g_h2);
    cudaGetSymbolAddress((void**)&p_deg, g_deg);

    const int smemI = 512 + 20 * 512 * 8 + 8 * 16 * 132 * 4;          // 150016
    const int smemN = 1536 + 36 * 512 * 8 + 8 * 16 * 132 * 4;         // 216576
    cudaFuncSetAttribute(k_input, cudaFuncAttributeMaxDynamicSharedMemorySize, smemI);
    cudaFuncSetAttribute(k_node,  cudaFuncAttributeMaxDynamicSharedMemorySize, smemN);

    // CSR build
    cudaMemsetAsync(p_deg, 0, NN * sizeof(int));
    k_deg<<<(EE + 255) / 256, 256>>>(eidx + EE);
    k_scan<<<1, 1024>>>();
    k_scatter<<<(EE + 255) / 256, 256>>>(eidx, eidx + EE, erel);

    // input projection (tf32 mma)
    k_input<<<148, 256, smemI>>>(x, label, lemb, Win, bin, p_h);

    const float* hin = p_h;
    for (int l = 0; l < 2; l++) {
        float* hout = (l == 0) ? p_h2 : out;
        k_gather<<<(NN + 7) / 8, 256>>>(hin, relemb + l * 1024 * RD);
        k_node<<<148, 256, smemN>>>(hin,
                                    Wself + l * DM * DM, Wn + l * DM * DM,
                                    Wr + l * RD * DM, bself + l * DM,
                                    lng + l * DM, lnb + l * DM, hout);
        hin = hout;
    }
}

// round 10
// speedup vs baseline: 1.4715x; 1.1263x over previous
#include <cuda_runtime.h>

#define NN 50000
#define EE 800000
#define DM 128
#define RD 32
#define LN_EPS 1e-5f
#define NT2 ((NN + 255) / 256)   // 196 tiles of 256 nodes

// ---------------- scratch ----------------------------------------------------
__device__ float g_h[NN * DM];
__device__ float g_h2[NN * DM];
__device__ float g_aggH[NN * DM];
__device__ float g_aggR[NN * RD];
__device__ float g_inv[NN];
__device__ int   g_deg[NN];
__device__ int   g_off[NN + 1];
__device__ int   g_cur[NN];
__device__ int2  g_csr[EE];        // (src, rel) grouped by dst

// ---------------- CSR build ----------------------------------------------------
__global__ void k_deg(const int* __restrict__ dst) {
    int i = blockIdx.x * blockDim.x + threadIdx.x;
    if (i < EE) atomicAdd(&g_deg[dst[i]], 1);
}

__global__ __launch_bounds__(1024) void k_scan() {
    __shared__ int wsum[32];
    __shared__ int sh_carry;
    int t = threadIdx.x, lane = t & 31, w = t >> 5;
    if (t == 0) sh_carry = 0;
    __syncthreads();

    for (int base = 0; base < NN; base += 1024) {
        int idx = base + t;
        int d = (idx < NN) ? g_deg[idx] : 0;
        int carry = sh_carry;

        int incl = d;
        #pragma unroll
        for (int o = 1; o < 32; o <<= 1) {
            int u = __shfl_up_sync(0xffffffffu, incl, o);
            if (lane >= o) incl += u;
        }
        if (lane == 31) wsum[w] = incl;
        __syncthreads();
        if (w == 0) {
            int u = wsum[lane];
            #pragma unroll
            for (int o = 1; o < 32; o <<= 1) {
                int uu = __shfl_up_sync(0xffffffffu, u, o);
                if (lane >= o) u += uu;
            }
            wsum[lane] = u;
        }
        __syncthreads();

        int excl = carry + (w > 0 ? wsum[w - 1] : 0) + incl - d;
        if (idx < NN) {
            g_off[idx] = excl;
            g_cur[idx] = excl;
            g_inv[idx] = d > 0 ? (1.f / (float)d) : 0.f;
        }
        int total = wsum[31];
        __syncthreads();
        if (t == 0) sh_carry = carry + total;
        __syncthreads();
    }
    if (t == 0) g_off[NN] = EE;
}

__global__ void k_scatter(const int* __restrict__ src, const int* __restrict__ dst,
                          const int* __restrict__ erel) {
    int i = blockIdx.x * blockDim.x + threadIdx.x;
    if (i < EE) {
        int d = dst[i];
        int pos = atomicAdd(&g_cur[d], 1);
        g_csr[pos] = make_int2(src[i], erel[i]);
    }
}

// ---------------- gather (fp32): aggH[v]=mean h[src], aggR[v]=mean rel ---------
__global__ __launch_bounds__(256) void k_gather(
    const float* __restrict__ hin, const float* __restrict__ rel)
{
    __shared__ int2 stage[8][32];
    int w = threadIdx.x >> 5, lane = threadIdx.x & 31;
    int v = blockIdx.x * 8 + w;
    if (v >= NN) return;
    int2* st = stage[w];

    int e = g_off[v], end = g_off[v + 1];
    float4 a0 = make_float4(0.f, 0.f, 0.f, 0.f), a1 = a0, a2 = a0, a3 = a0;
    float r0s = 0.f, r1s = 0.f, r2s = 0.f, r3s = 0.f;

    while (e < end) {
        int n = min(32, end - e);
        if (lane < n) st[lane] = g_csr[e + lane];
        __syncwarp();
        int j = 0;
        for (; j + 4 <= n; j += 4) {
            int2 p0 = st[j], p1 = st[j + 1], p2 = st[j + 2], p3 = st[j + 3];
            float4 h0 = ((const float4*)(hin + (size_t)p0.x * DM))[lane];
            float4 h1 = ((const float4*)(hin + (size_t)p1.x * DM))[lane];
            float4 h2 = ((const float4*)(hin + (size_t)p2.x * DM))[lane];
            float4 h3 = ((const float4*)(hin + (size_t)p3.x * DM))[lane];
            float q0 = rel[p0.y * RD + lane];
            float q1 = rel[p1.y * RD + lane];
            float q2 = rel[p2.y * RD + lane];
            float q3 = rel[p3.y * RD + lane];
            a0.x += h0.x; a0.y += h0.y; a0.z += h0.z; a0.w += h0.w;
            a1.x += h1.x; a1.y += h1.y; a1.z += h1.z; a1.w += h1.w;
            a2.x += h2.x; a2.y += h2.y; a2.z += h2.z; a2.w += h2.w;
            a3.x += h3.x; a3.y += h3.y; a3.z += h3.z; a3.w += h3.w;
            r0s += q0; r1s += q1; r2s += q2; r3s += q3;
        }
        for (; j < n; j++) {
            int2 p0 = st[j];
            float4 h0 = ((const float4*)(hin + (size_t)p0.x * DM))[lane];
            a0.x += h0.x; a0.y += h0.y; a0.z += h0.z; a0.w += h0.w;
            r0s += rel[p0.y * RD + lane];
        }
        e += n;
        __syncwarp();
    }

    float iv = g_inv[v];
    float4 acc;
    acc.x = (a0.x + a1.x + a2.x + a3.x) * iv;
    acc.y = (a0.y + a1.y + a2.y + a3.y) * iv;
    acc.z = (a0.z + a1.z + a2.z + a3.z) * iv;
    acc.w = (a0.w + a1.w + a2.w + a3.w) * iv;
    ((float4*)(g_aggH + (size_t)v * DM))[lane] = acc;
    g_aggR[v * RD + lane] = (r0s + r1s + r2s + r3s) * iv;
}

// ---------------- tf32 mma machinery -------------------------------------------
extern __shared__ float smdyn[];

__device__ __forceinline__ unsigned f2tf(float f) {
    unsigned r;
    asm("cvt.rna.tf32.f32 %0, %1;" : "=r"(r) : "f"(f));
    return r;
}

#define MMA_T(CI, A0, A1, A2, A3, BX, BY)                                       \
    asm("mma.sync.aligned.m16n8k8.row.col.f32.tf32.tf32.f32 "                   \
        "{%0,%1,%2,%3},{%4,%5,%6,%7},{%8,%9},{%0,%1,%2,%3};"                    \
        : "+f"(c[(CI)]), "+f"(c[(CI)+1]), "+f"(c[(CI)+2]), "+f"(c[(CI)+3])      \
        : "r"(A0), "r"(A1), "r"(A2), "r"(A3), "r"(BX), "r"(BY));

#define MMA_ROW16(BP)                                                           \
    _Pragma("unroll")                                                           \
    for (int nt = 0; nt < 16; nt++) {                                           \
        uint2 b = (BP)[nt * 32];                                                \
        MMA_T(nt * 4, a0, a1, a2, a3, b.x, b.y)                                 \
    }

// ---------------- input projection: h = relu([x, lemb[label]] @ W + b) ---------
__global__ __launch_bounds__(512) void k_input(
    const float* __restrict__ x, const int* __restrict__ label,
    const float* __restrict__ lemb, const float* __restrict__ W,
    const float* __restrict__ b, float* __restrict__ hout)
{
    float* bs = smdyn;                       // 128 floats
    uint2* Bp = (uint2*)(bs + DM);           // 20*512 uint2

    int tid = threadIdx.x;
    for (int idx = tid; idx < 20 * 512; idx += 512) {
        int kk = idx >> 9, r = idx & 511;
        int nt = r >> 5, ln = r & 31;
        int qq = ln & 3, gg = ln >> 2;
        int col = nt * 8 + gg;
        int k0 = kk * 8 + qq;
        Bp[idx] = make_uint2(f2tf(W[k0 * DM + col]), f2tf(W[(k0 + 4) * DM + col]));
    }
    for (int i = tid; i < DM; i += 512) bs[i] = b[i];
    __syncthreads();

    int w = tid >> 5, lane = tid & 31, q = lane & 3, g = lane >> 2;
    const uint2* bpl = Bp + lane;

    for (int tb = blockIdx.x; tb < NT2; tb += gridDim.x) {
        int v0w = tb * 256 + w * 16;
        if (v0w >= NN) continue;
        int va = min(v0w + g, NN - 1);
        int vb = min(v0w + g + 8, NN - 1);
        int la = __ldg(&label[va]);
        int lb = __ldg(&label[vb]);

        float c[64];
        #pragma unroll
        for (int i = 0; i < 64; i++) c[i] = 0.f;

        #pragma unroll 4
        for (int kk = 0; kk < 16; kk++) {
            unsigned a0 = f2tf(x[(size_t)va * DM + kk * 8 + q]);
            unsigned a2 = f2tf(x[(size_t)va * DM + kk * 8 + q + 4]);
            unsigned a1 = f2tf(x[(size_t)vb * DM + kk * 8 + q]);
            unsigned a3 = f2tf(x[(size_t)vb * DM + kk * 8 + q + 4]);
            const uint2* bp = bpl + kk * 512;
            MMA_ROW16(bp)
        }
        #pragma unroll
        for (int kk = 0; kk < 4; kk++) {
            unsigned a0 = f2tf(lemb[la * RD + kk * 8 + q]);
            unsigned a2 = f2tf(lemb[la * RD + kk * 8 + q + 4]);
            unsigned a1 = f2tf(lemb[lb * RD + kk * 8 + q]);
            unsigned a3 = f2tf(lemb[lb * RD + kk * 8 + q + 4]);
            const uint2* bp = bpl + (kk + 16) * 512;
            MMA_ROW16(bp)
        }

        // register epilogue: bias + relu, direct float2 stores
        int ra = v0w + g, rb = v0w + g + 8;
        #pragma unroll
        for (int nt = 0; nt < 16; nt++) {
            float2 bv = *(float2*)(bs + nt * 8 + 2 * q);
            if (ra < NN) {
                float2 o = make_float2(fmaxf(c[nt*4+0] + bv.x, 0.f),
                                       fmaxf(c[nt*4+1] + bv.y, 0.f));
                *(float2*)(hout + (size_t)ra * DM + nt * 8 + 2 * q) = o;
            }
            if (rb < NN) {
                float2 o = make_float2(fmaxf(c[nt*4+2] + bv.x, 0.f),
                                       fmaxf(c[nt*4+3] + bv.y, 0.f));
                *(float2*)(hout + (size_t)rb * DM + nt * 8 + 2 * q) = o;
            }
        }
    }
}

// ---------------- node pass: tf32 mma 3-GEMM + bias + relu + layernorm ---------
__global__ __launch_bounds__(512) void k_node(
    const float* __restrict__ hin,
    const float* __restrict__ Wself, const float* __restrict__ Wn,
    const float* __restrict__ Wr, const float* __restrict__ bias,
    const float* __restrict__ lng, const float* __restrict__ lnb,
    float* __restrict__ hout)
{
    float* bs  = smdyn;                      // 128
    float* gs  = bs + DM;                    // 128
    float* lbs = gs + DM;                    // 128
    uint2* Bp  = (uint2*)(lbs + DM);         // 36*512 uint2

    int tid = threadIdx.x;
    for (int idx = tid; idx < 36 * 512; idx += 512) {
        int kk = idx >> 9, r = idx & 511;
        int nt = r >> 5, ln = r & 31;
        int qq = ln & 3, gg = ln >> 2;
        int col = nt * 8 + gg;
        int k0 = kk * 8 + qq;
        float w0, w1;
        if (k0 < 128)      { w0 = Wself[k0 * DM + col];        w1 = Wself[(k0 + 4) * DM + col]; }
        else if (k0 < 256) { w0 = Wn[(k0 - 128) * DM + col];   w1 = Wn[(k0 - 124) * DM + col]; }
        else               { w0 = Wr[(k0 - 256) * DM + col];   w1 = Wr[(k0 - 252) * DM + col]; }
        Bp[idx] = make_uint2(f2tf(w0), f2tf(w1));
    }
    for (int i = tid; i < DM; i += 512) {
        bs[i] = bias[i]; gs[i] = lng[i]; lbs[i] = lnb[i];
    }
    __syncthreads();

    int w = tid >> 5, lane = tid & 31, q = lane & 3, g = lane >> 2;
    const uint2* bpl = Bp + lane;

    for (int tb = blockIdx.x; tb < NT2; tb += gridDim.x) {
        int v0w = tb * 256 + w * 16;
        if (v0w >= NN) continue;
        int va = min(v0w + g, NN - 1);
        int vb = min(v0w + g + 8, NN - 1);

        float c[64];
        #pragma unroll
        for (int i = 0; i < 64; i++) c[i] = 0.f;

        #pragma unroll 4
        for (int kk = 0; kk < 16; kk++) {
            unsigned a0 = f2tf(hin[(size_t)va * DM + kk * 8 + q]);
            unsigned a2 = f2tf(hin[(size_t)va * DM + kk * 8 + q + 4]);
            unsigned a1 = f2tf(hin[(size_t)vb * DM + kk * 8 + q]);
            unsigned a3 = f2tf(hin[(size_t)vb * DM + kk * 8 + q + 4]);
            const uint2* bp = bpl + kk * 512;
            MMA_ROW16(bp)
        }
        #pragma unroll 4
        for (int kk = 0; kk < 16; kk++) {
            unsigned a0 = f2tf(g_aggH[(size_t)va * DM + kk * 8 + q]);
            unsigned a2 = f2tf(g_aggH[(size_t)va * DM + kk * 8 + q + 4]);
            unsigned a1 = f2tf(g_aggH[(size_t)vb * DM + kk * 8 + q]);
            unsigned a3 = f2tf(g_aggH[(size_t)vb * DM + kk * 8 + q + 4]);
            const uint2* bp = bpl + (kk + 16) * 512;
            MMA_ROW16(bp)
        }
        #pragma unroll
        for (int kk = 0; kk < 4; kk++) {
            unsigned a0 = f2tf(g_aggR[(size_t)va * RD + kk * 8 + q]);
            unsigned a2 = f2tf(g_aggR[(size_t)va * RD + kk * 8 + q + 4]);
            unsigned a1 = f2tf(g_aggR[(size_t)vb * RD + kk * 8 + q]);
            unsigned a3 = f2tf(g_aggR[(size_t)vb * RD + kk * 8 + q + 4]);
            const uint2* bp = bpl + (kk + 32) * 512;
            MMA_ROW16(bp)
        }

        // register epilogue: bias + relu + LN (quad-shuffle stats) + store
        float s1a = 0.f, s2a = 0.f, s1b = 0.f, s2b = 0.f;
        #pragma unroll
        for (int nt = 0; nt < 16; nt++) {
            float2 bv = *(float2*)(bs + nt * 8 + 2 * q);
            float c0 = fmaxf(c[nt*4+0] + bv.x, 0.f);
            float c1 = fmaxf(c[nt*4+1] + bv.y, 0.f);
            float c2 = fmaxf(c[nt*4+2] + bv.x, 0.f);
            float c3 = fmaxf(c[nt*4+3] + bv.y, 0.f);
            c[nt*4+0] = c0; c[nt*4+1] = c1; c[nt*4+2] = c2; c[nt*4+3] = c3;
            s1a += c0 + c1; s2a += c0 * c0 + c1 * c1;
            s1b += c2 + c3; s2b += c2 * c2 + c3 * c3;
        }
        #pragma unroll
        for (int m = 1; m <= 2; m <<= 1) {
            s1a += __shfl_xor_sync(0xffffffffu, s1a, m);
            s2a += __shfl_xor_sync(0xffffffffu, s2a, m);
            s1b += __shfl_xor_sync(0xffffffffu, s1b, m);
            s2b += __shfl_xor_sync(0xffffffffu, s2b, m);
        }
        float mua = s1a * (1.f / 128.f);
        float rsa = rsqrtf(s2a * (1.f / 128.f) - mua * mua + LN_EPS);
        float mub = s1b * (1.f / 128.f);
        float rsb = rsqrtf(s2b * (1.f / 128.f) - mub * mub + LN_EPS);

        int ra = v0w + g, rb = v0w + g + 8;
        #pragma unroll
        for (int nt = 0; nt < 16; nt++) {
            float2 gv = *(float2*)(gs + nt * 8 + 2 * q);
            float2 lv = *(float2*)(lbs + nt * 8 + 2 * q);
            if (ra < NN) {
                float2 o = make_float2((c[nt*4+0] - mua) * rsa * gv.x + lv.x,
                                       (c[nt*4+1] - mua) * rsa * gv.y + lv.y);
                *(float2*)(hout + (size_t)ra * DM + nt * 8 + 2 * q) = o;
            }
            if (rb < NN) {
                float2 o = make_float2((c[nt*4+2] - mub) * rsb * gv.x + lv.x,
                                       (c[nt*4+3] - mub) * rsb * gv.y + lv.y);
                *(float2*)(hout + (size_t)rb * DM + nt * 8 + 2 * q) = o;
            }
        }
    }
}

// ---------------- host launch ------------------------------------------------------
extern "C" void kernel_launch(void* const* d_in, const int* in_sizes, int n_in,
                              void* d_out, int out_size)
{
    const float* x      = (const float*)d_in[0];
    const int*   label  = (const int*)d_in[1];
    const int*   eidx   = (const int*)d_in[2];
    const int*   erel   = (const int*)d_in[3];
    const float* lemb   = (const float*)d_in[4];
    const float* Win    = (const float*)d_in[5];
    const float* bin    = (const float*)d_in[6];
    const float* relemb = (const float*)d_in[7];
    const float* Wn     = (const float*)d_in[8];
    const float* Wself  = (const float*)d_in[9];
    const float* bself  = (const float*)d_in[10];
    const float* Wr     = (const float*)d_in[11];
    const float* lng    = (const float*)d_in[12];
    const float* lnb    = (const float*)d_in[13];
    float* out = (float*)d_out;

    float *p_h, *p_h2;
    int *p_deg;
    cudaGetSymbolAddress((void**)&p_h,   g_h);
    cudaGetSymbolAddress((void**)&p_h2,  g_h2);
    cudaGetSymbolAddress((void**)&p_deg, g_deg);

    const int smemI = 512 + 20 * 512 * 8;          // 82432
    const int smemN = 1536 + 36 * 512 * 8;         // 148992
    cudaFuncSetAttribute(k_input, cudaFuncAttributeMaxDynamicSharedMemorySize, smemI);
    cudaFuncSetAttribute(k_node,  cudaFuncAttributeMaxDynamicSharedMemorySize, smemN);

    // CSR build
    cudaMemsetAsync(p_deg, 0, NN * sizeof(int));
    k_deg<<<(EE + 255) / 256, 256>>>(eidx + EE);
    k_scan<<<1, 1024>>>();
    k_scatter<<<(EE + 255) / 256, 256>>>(eidx, eidx + EE, erel);

    // input projection (tf32 mma, 512 thr)
    k_input<<<148, 512, smemI>>>(x, label, lemb, Win, bin, p_h);

    const float* hin = p_h;
    for (int l = 0; l < 2; l++) {
        float* hout = (l == 0) ? p_h2 : out;
        k_gather<<<(NN + 7) / 8, 256>>>(hin, relemb + l * 1024 * RD);
        k_node<<<148, 512, smemN>>>(hin,
                                    Wself + l * DM * DM, Wn + l * DM * DM,
                                    Wr + l * RD * DM, bself + l * DM,
                                    lng + l * DM, lnb + l * DM, hout);
        hin = hout;
    }
}

// round 12
// speedup vs baseline: 1.8689x; 1.2701x over previous
#include <cuda_runtime.h>
#include <cuda_fp16.h>

#define NN 50000
#define EE 800000
#define DM 128
#define RD 32
#define LN_EPS 1e-5f
#define NT2 ((NN + 255) / 256)   // 196 tiles of 256 nodes

// ---------------- scratch ----------------------------------------------------
__device__ float g_h[NN * DM];
__device__ float g_h2[NN * DM];
__device__ float g_aggH[NN * DM];
__device__ float g_aggR[NN * RD];
__device__ float g_inv[NN];
__device__ int   g_deg[NN];
__device__ int   g_off[NN + 1];
__device__ int   g_cur[NN];
__device__ int2  g_csr[EE];        // (src, rel) grouped by dst

// ---------------- CSR build ----------------------------------------------------
__global__ void k_deg(const int* __restrict__ dst) {
    int i = blockIdx.x * blockDim.x + threadIdx.x;
    if (i < EE) atomicAdd(&g_deg[dst[i]], 1);
}

__global__ __launch_bounds__(1024) void k_scan() {
    __shared__ int wsum[32];
    __shared__ int sh_carry;
    int t = threadIdx.x, lane = t & 31, w = t >> 5;
    if (t == 0) sh_carry = 0;
    __syncthreads();

    for (int base = 0; base < NN; base += 1024) {
        int idx = base + t;
        int d = (idx < NN) ? g_deg[idx] : 0;
        int carry = sh_carry;

        int incl = d;
        #pragma unroll
        for (int o = 1; o < 32; o <<= 1) {
            int u = __shfl_up_sync(0xffffffffu, incl, o);
            if (lane >= o) incl += u;
        }
        if (lane == 31) wsum[w] = incl;
        __syncthreads();
        if (w == 0) {
            int u = wsum[lane];
            #pragma unroll
            for (int o = 1; o < 32; o <<= 1) {
                int uu = __shfl_up_sync(0xffffffffu, u, o);
                if (lane >= o) u += uu;
            }
            wsum[lane] = u;
        }
        __syncthreads();

        int excl = carry + (w > 0 ? wsum[w - 1] : 0) + incl - d;
        if (idx < NN) {
            g_off[idx] = excl;
            g_cur[idx] = excl;
            g_inv[idx] = d > 0 ? (1.f / (float)d) : 0.f;
        }
        int total = wsum[31];
        __syncthreads();
        if (t == 0) sh_carry = carry + total;
        __syncthreads();
    }
    if (t == 0) g_off[NN] = EE;
}

__global__ void k_scatter(const int* __restrict__ src, const int* __restrict__ dst,
                          const int* __restrict__ erel) {
    int i = blockIdx.x * blockDim.x + threadIdx.x;
    if (i < EE) {
        int d = dst[i];
        int pos = atomicAdd(&g_cur[d], 1);
        g_csr[pos] = make_int2(src[i], erel[i]);
    }
}

// ---------------- gather (fp32): aggH[v]=mean h[src], aggR[v]=mean rel ---------
__global__ __launch_bounds__(256) void k_gather(
    const float* __restrict__ hin, const float* __restrict__ rel)
{
    __shared__ int2 stage[8][32];
    int w = threadIdx.x >> 5, lane = threadIdx.x & 31;
    int v = blockIdx.x * 8 + w;
    if (v >= NN) return;
    int2* st = stage[w];

    int e = g_off[v], end = g_off[v + 1];
    float4 a0 = make_float4(0.f, 0.f, 0.f, 0.f), a1 = a0, a2 = a0, a3 = a0;
    float r0s = 0.f, r1s = 0.f, r2s = 0.f, r3s = 0.f;

    while (e < end) {
        int n = min(32, end - e);
        if (lane < n) st[lane] = g_csr[e + lane];
        __syncwarp();
        int j = 0;
        for (; j + 4 <= n; j += 4) {
            int2 p0 = st[j], p1 = st[j + 1], p2 = st[j + 2], p3 = st[j + 3];
            float4 h0 = ((const float4*)(hin + (size_t)p0.x * DM))[lane];
            float4 h1 = ((const float4*)(hin + (size_t)p1.x * DM))[lane];
            float4 h2 = ((const float4*)(hin + (size_t)p2.x * DM))[lane];
            float4 h3 = ((const float4*)(hin + (size_t)p3.x * DM))[lane];
            float q0 = rel[p0.y * RD + lane];
            float q1 = rel[p1.y * RD + lane];
            float q2 = rel[p2.y * RD + lane];
            float q3 = rel[p3.y * RD + lane];
            a0.x += h0.x; a0.y += h0.y; a0.z += h0.z; a0.w += h0.w;
            a1.x += h1.x; a1.y += h1.y; a1.z += h1.z; a1.w += h1.w;
            a2.x += h2.x; a2.y += h2.y; a2.z += h2.z; a2.w += h2.w;
            a3.x += h3.x; a3.y += h3.y; a3.z += h3.z; a3.w += h3.w;
            r0s += q0; r1s += q1; r2s += q2; r3s += q3;
        }
        for (; j < n; j++) {
            int2 p0 = st[j];
            float4 h0 = ((const float4*)(hin + (size_t)p0.x * DM))[lane];
            a0.x += h0.x; a0.y += h0.y; a0.z += h0.z; a0.w += h0.w;
            r0s += rel[p0.y * RD + lane];
        }
        e += n;
        __syncwarp();
    }

    float iv = g_inv[v];
    float4 acc;
    acc.x = (a0.x + a1.x + a2.x + a3.x) * iv;
    acc.y = (a0.y + a1.y + a2.y + a3.y) * iv;
    acc.z = (a0.z + a1.z + a2.z + a3.z) * iv;
    acc.w = (a0.w + a1.w + a2.w + a3.w) * iv;
    ((float4*)(g_aggH + (size_t)v * DM))[lane] = acc;
    g_aggR[v * RD + lane] = (r0s + r1s + r2s + r3s) * iv;
}

// ---------------- fp16 mma machinery --------------------------------------------
extern __shared__ float smdyn[];

__device__ __forceinline__ unsigned ldh2(const float* p) {
    float2 f = *(const float2*)p;
    __half2 h = __float22half2_rn(f);
    return *(unsigned*)&h;
}
__device__ __forceinline__ unsigned packh2(float a, float b) {
    __half2 h = __floats2half2_rn(a, b);
    return *(unsigned*)&h;
}

// c[CI..CI+3] += A(16x16) * B(16x8), fp16 inputs, fp32 accum
#define MMA_H(CI, A0, A1, A2, A3, B0, B1)                                       \
    asm("mma.sync.aligned.m16n8k16.row.col.f32.f16.f16.f32 "                    \
        "{%0,%1,%2,%3},{%4,%5,%6,%7},{%8,%9},{%0,%1,%2,%3};"                    \
        : "+f"(c[(CI)]), "+f"(c[(CI)+1]), "+f"(c[(CI)+2]), "+f"(c[(CI)+3])      \
        : "r"(A0), "r"(A1), "r"(A2), "r"(A3), "r"(B0), "r"(B1));

#define MMA_ROW16H(BP)                                                          \
    _Pragma("unroll")                                                           \
    for (int nt = 0; nt < 16; nt++) {                                           \
        uint2 b = (BP)[nt * 32];                                                \
        MMA_H(nt * 4, a0, a1, a2, a3, b.x, b.y)                                 \
    }

// B fragment staging: for k-step kk (K=16), n-tile nt, lane ln:
//   n = nt*8 + ln/4, kb = kk*16 + (ln&3)*2
//   reg0 = half2(W[kb][n], W[kb+1][n]); reg1 = half2(W[kb+8][n], W[kb+9][n])

// ---------------- input projection: h = relu([x, lemb[label]] @ W + b) ---------
// K = 160 -> 10 k-steps (8 from x, 2 from label emb)
__global__ __launch_bounds__(512) void k_input(
    const float* __restrict__ x, const int* __restrict__ label,
    const float* __restrict__ lemb, const float* __restrict__ W,
    const float* __restrict__ b, float* __restrict__ hout)
{
    float* bs = smdyn;                       // 128 floats
    uint2* Bp = (uint2*)(bs + DM);           // 10*512 uint2

    int tid = threadIdx.x;
    for (int idx = tid; idx < 10 * 512; idx += 512) {
        int kk = idx >> 9, r = idx & 511;
        int nt = r >> 5, ln = r & 31;
        int n = nt * 8 + (ln >> 2);
        int kb = kk * 16 + (ln & 3) * 2;
        unsigned r0 = packh2(W[kb * DM + n],       W[(kb + 1) * DM + n]);
        unsigned r1 = packh2(W[(kb + 8) * DM + n], W[(kb + 9) * DM + n]);
        Bp[idx] = make_uint2(r0, r1);
    }
    for (int i = tid; i < DM; i += 512) bs[i] = b[i];
    __syncthreads();

    int w = tid >> 5, lane = tid & 31, q = lane & 3, g = lane >> 2;
    const uint2* bpl = Bp + lane;

    for (int tb = blockIdx.x; tb < NT2; tb += gridDim.x) {
        int v0w = tb * 256 + w * 16;
        if (v0w >= NN) continue;
        int va = min(v0w + g, NN - 1);
        int vb = min(v0w + g + 8, NN - 1);
        int la = __ldg(&label[va]);
        int lb = __ldg(&label[vb]);

        float c[64];
        #pragma unroll
        for (int i = 0; i < 64; i++) c[i] = 0.f;

        #pragma unroll
        for (int kk = 0; kk < 8; kk++) {
            int kb = kk * 16 + q * 2;
            unsigned a0 = ldh2(x + (size_t)va * DM + kb);
            unsigned a1 = ldh2(x + (size_t)vb * DM + kb);
            unsigned a2 = ldh2(x + (size_t)va * DM + kb + 8);
            unsigned a3 = ldh2(x + (size_t)vb * DM + kb + 8);
            const uint2* bp = bpl + kk * 512;
            MMA_ROW16H(bp)
        }
        #pragma unroll
        for (int kk = 8; kk < 10; kk++) {
            int kb = kk * 16 + q * 2 - 128;
            unsigned a0 = ldh2(lemb + (size_t)la * RD + kb);
            unsigned a1 = ldh2(lemb + (size_t)lb * RD + kb);
            unsigned a2 = ldh2(lemb + (size_t)la * RD + kb + 8);
            unsigned a3 = ldh2(lemb + (size_t)lb * RD + kb + 8);
            const uint2* bp = bpl + kk * 512;
            MMA_ROW16H(bp)
        }

        // register epilogue: bias + relu, direct float2 stores
        int ra = v0w + g, rb = v0w + g + 8;
        #pragma unroll
        for (int nt = 0; nt < 16; nt++) {
            float2 bv = *(float2*)(bs + nt * 8 + 2 * q);
            if (ra < NN) {
                float2 o = make_float2(fmaxf(c[nt*4+0] + bv.x, 0.f),
                                       fmaxf(c[nt*4+1] + bv.y, 0.f));
                *(float2*)(hout + (size_t)ra * DM + nt * 8 + 2 * q) = o;
            }
            if (rb < NN) {
                float2 o = make_float2(fmaxf(c[nt*4+2] + bv.x, 0.f),
                                       fmaxf(c[nt*4+3] + bv.y, 0.f));
                *(float2*)(hout + (size_t)rb * DM + nt * 8 + 2 * q) = o;
            }
        }
    }
}

// ---------------- node pass: fp16 mma 3-GEMM + bias + relu + layernorm ---------
// K = 288 -> 18 k-steps (8 from h, 8 from aggH, 2 from aggR)
__global__ __launch_bounds__(512) void k_node(
    const float* __restrict__ hin,
    const float* __restrict__ Wself, const float* __restrict__ Wn,
    const float* __restrict__ Wr, const float* __restrict__ bias,
    const float* __restrict__ lng, const float* __restrict__ lnb,
    float* __restrict__ hout)
{
    float* bs  = smdyn;                      // 128
    float* gs  = bs + DM;                    // 128
    float* lbs = gs + DM;                    // 128
    uint2* Bp  = (uint2*)(lbs + DM);         // 18*512 uint2

    int tid = threadIdx.x;
    for (int idx = tid; idx < 18 * 512; idx += 512) {
        int kk = idx >> 9, r = idx & 511;
        int nt = r >> 5, ln = r & 31;
        int n = nt * 8 + (ln >> 2);
        int kb = kk * 16 + (ln & 3) * 2;
        float w00, w01, w10, w11;
        if (kb < 128) {
            w00 = Wself[kb * DM + n];       w01 = Wself[(kb + 1) * DM + n];
            w10 = Wself[(kb + 8) * DM + n]; w11 = Wself[(kb + 9) * DM + n];
        } else if (kb < 256) {
            int k2 = kb - 128;
            w00 = Wn[k2 * DM + n];          w01 = Wn[(k2 + 1) * DM + n];
            w10 = Wn[(k2 + 8) * DM + n];    w11 = Wn[(k2 + 9) * DM + n];
        } else {
            int k2 = kb - 256;
            w00 = Wr[k2 * DM + n];          w01 = Wr[(k2 + 1) * DM + n];
            w10 = Wr[(k2 + 8) * DM + n];    w11 = Wr[(k2 + 9) * DM + n];
        }
        Bp[idx] = make_uint2(packh2(w00, w01), packh2(w10, w11));
    }
    for (int i = tid; i < DM; i += 512) {
        bs[i] = bias[i]; gs[i] = lng[i]; lbs[i] = lnb[i];
    }
    __syncthreads();

    int w = tid >> 5, lane = tid & 31, q = lane & 3, g = lane >> 2;
    const uint2* bpl = Bp + lane;

    for (int tb = blockIdx.x; tb < NT2; tb += gridDim.x) {
        int v0w = tb * 256 + w * 16;
        if (v0w >= NN) continue;
        int va = min(v0w + g, NN - 1);
        int vb = min(v0w + g + 8, NN - 1);

        float c[64];
        #pragma unroll
        for (int i = 0; i < 64; i++) c[i] = 0.f;

        #pragma unroll
        for (int kk = 0; kk < 8; kk++) {
            int kb = kk * 16 + q * 2;
            unsigned a0 = ldh2(hin + (size_t)va * DM + kb);
            unsigned a1 = ldh2(hin + (size_t)vb * DM + kb);
            unsigned a2 = ldh2(hin + (size_t)va * DM + kb + 8);
            unsigned a3 = ldh2(hin + (size_t)vb * DM + kb + 8);
            const uint2* bp = bpl + kk * 512;
            MMA_ROW16H(bp)
        }
        #pragma unroll
        for (int kk = 8; kk < 16; kk++) {
            int kb = kk * 16 + q * 2 - 128;
            unsigned a0 = ldh2(g_aggH + (size_t)va * DM + kb);
            unsigned a1 = ldh2(g_aggH + (size_t)vb * DM + kb);
            unsigned a2 = ldh2(g_aggH + (size_t)va * DM + kb + 8);
            unsigned a3 = ldh2(g_aggH + (size_t)vb * DM + kb + 8);
            const uint2* bp = bpl + kk * 512;
            MMA_ROW16H(bp)
        }
        #pragma unroll
        for (int kk = 16; kk < 18; kk++) {
            int kb = kk * 16 + q * 2 - 256;
            unsigned a0 = ldh2(g_aggR + (size_t)va * RD + kb);
            unsigned a1 = ldh2(g_aggR + (size_t)vb * RD + kb);
            unsigned a2 = ldh2(g_aggR + (size_t)va * RD + kb + 8);
            unsigned a3 = ldh2(g_aggR + (size_t)vb * RD + kb + 8);
            const uint2* bp = bpl + kk * 512;
            MMA_ROW16H(bp)
        }

        // register epilogue: bias + relu + LN (quad-shuffle stats) + store
        float s1a = 0.f, s2a = 0.f, s1b = 0.f, s2b = 0.f;
        #pragma unroll
        for (int nt = 0; nt < 16; nt++) {
            float2 bv = *(float2*)(bs + nt * 8 + 2 * q);
            float c0 = fmaxf(c[nt*4+0] + bv.x, 0.f);
            float c1 = fmaxf(c[nt*4+1] + bv.y, 0.f);
            float c2 = fmaxf(c[nt*4+2] + bv.x, 0.f);
            float c3 = fmaxf(c[nt*4+3] + bv.y, 0.f);
            c[nt*4+0] = c0; c[nt*4+1] = c1; c[nt*4+2] = c2; c[nt*4+3] = c3;
            s1a += c0 + c1; s2a += c0 * c0 + c1 * c1;
            s1b += c2 + c3; s2b += c2 * c2 + c3 * c3;
        }
        #pragma unroll
        for (int m = 1; m <= 2; m <<= 1) {
            s1a += __shfl_xor_sync(0xffffffffu, s1a, m);
            s2a += __shfl_xor_sync(0xffffffffu, s2a, m);
            s1b += __shfl_xor_sync(0xffffffffu, s1b, m);
            s2b += __shfl_xor_sync(0xffffffffu, s2b, m);
        }
        float mua = s1a * (1.f / 128.f);
        float rsa = rsqrtf(s2a * (1.f / 128.f) - mua * mua + LN_EPS);
        float mub = s1b * (1.f / 128.f);
        float rsb = rsqrtf(s2b * (1.f / 128.f) - mub * mub + LN_EPS);

        int ra = v0w + g, rb = v0w + g + 8;
        #pragma unroll
        for (int nt = 0; nt < 16; nt++) {
            float2 gv = *(float2*)(gs + nt * 8 + 2 * q);
            float2 lv = *(float2*)(lbs + nt * 8 + 2 * q);
            if (ra < NN) {
                float2 o = make_float2((c[nt*4+0] - mua) * rsa * gv.x + lv.x,
                                       (c[nt*4+1] - mua) * rsa * gv.y + lv.y);
                *(float2*)(hout + (size_t)ra * DM + nt * 8 + 2 * q) = o;
            }
            if (rb < NN) {
                float2 o = make_float2((c[nt*4+2] - mub) * rsb * gv.x + lv.x,
                                       (c[nt*4+3] - mub) * rsb * gv.y + lv.y);
                *(float2*)(hout + (size_t)rb * DM + nt * 8 + 2 * q) = o;
            }
        }
    }
}

// ---------------- host launch ------------------------------------------------------
extern "C" void kernel_launch(void* const* d_in, const int* in_sizes, int n_in,
                              void* d_out, int out_size)
{
    const float* x      = (const float*)d_in[0];
    const int*   label  = (const int*)d_in[1];
    const int*   eidx   = (const int*)d_in[2];
    const int*   erel   = (const int*)d_in[3];
    const float* lemb   = (const float*)d_in[4];
    const float* Win    = (const float*)d_in[5];
    const float* bin    = (const float*)d_in[6];
    const float* relemb = (const float*)d_in[7];
    const float* Wn     = (const float*)d_in[8];
    const float* Wself  = (const float*)d_in[9];
    const float* bself  = (const float*)d_in[10];
    const float* Wr     = (const float*)d_in[11];
    const float* lng    = (const float*)d_in[12];
    const float* lnb    = (const float*)d_in[13];
    float* out = (float*)d_out;

    float *p_h, *p_h2;
    int *p_deg;
    cudaGetSymbolAddress((void**)&p_h,   g_h);
    cudaGetSymbolAddress((void**)&p_h2,  g_h2);
    cudaGetSymbolAddress((void**)&p_deg, g_deg);

    const int smemI = 512 + 10 * 512 * 8;          // 41472
    const int smemN = 1536 + 18 * 512 * 8;         // 75264
    cudaFuncSetAttribute(k_input, cudaFuncAttributeMaxDynamicSharedMemorySize, smemI);
    cudaFuncSetAttribute(k_node,  cudaFuncAttributeMaxDynamicSharedMemorySize, smemN);

    // CSR build
    cudaMemsetAsync(p_deg, 0, NN * sizeof(int));
    k_deg<<<(EE + 255) / 256, 256>>>(eidx + EE);
    k_scan<<<1, 1024>>>();
    k_scatter<<<(EE + 255) / 256, 256>>>(eidx, eidx + EE, erel);

    // input projection (fp16 mma, 512 thr)
    k_input<<<148, 512, smemI>>>(x, label, lemb, Win, bin, p_h);

    const float* hin = p_h;
    for (int l = 0; l < 2; l++) {
        float* hout = (l == 0) ? p_h2 : out;
        k_gather<<<(NN + 7) / 8, 256>>>(hin, relemb + l * 1024 * RD);
        k_node<<<148, 512, smemN>>>(hin,
                                    Wself + l * DM * DM, Wn + l * DM * DM,
                                    Wr + l * RD * DM, bself + l * DM,
                                    lng + l * DM, lnb + l * DM, hout);
        hin = hout;
    }
}

// round 13
// speedup vs baseline: 2.0222x; 1.0820x over previous
#include <cuda_runtime.h>
#include <cuda_fp16.h>

#define NN 50000
#define EE 800000
#define DM 128
#define RD 32
#define LN_EPS 1e-5f
#define NT2 ((NN + 255) / 256)   // 196 tiles of 256 nodes

// ---------------- scratch (fp16 intermediates) ---------------------------------
__device__ __half g_hA[NN * DM];     // h after input proj (layer-0 input)
__device__ __half g_hB[NN * DM];     // layer-0 output (layer-1 input)
__device__ __half g_aggH[NN * DM];
__device__ __half g_aggR[NN * RD];
__device__ float  g_inv[NN];
__device__ int    g_deg[NN];
__device__ int    g_off[NN + 1];
__device__ int    g_cur[NN];
__device__ int2   g_csr[EE];         // (src, rel) grouped by dst

// ---------------- CSR build ----------------------------------------------------
__global__ void k_deg(const int* __restrict__ dst) {
    int i = blockIdx.x * blockDim.x + threadIdx.x;
    if (i < EE) atomicAdd(&g_deg[dst[i]], 1);
}

__global__ __launch_bounds__(1024) void k_scan() {
    __shared__ int wsum[32];
    __shared__ int sh_carry;
    int t = threadIdx.x, lane = t & 31, w = t >> 5;
    if (t == 0) sh_carry = 0;
    __syncthreads();

    for (int base = 0; base < NN; base += 1024) {
        int idx = base + t;
        int d = (idx < NN) ? g_deg[idx] : 0;
        int carry = sh_carry;

        int incl = d;
        #pragma unroll
        for (int o = 1; o < 32; o <<= 1) {
            int u = __shfl_up_sync(0xffffffffu, incl, o);
            if (lane >= o) incl += u;
        }
        if (lane == 31) wsum[w] = incl;
        __syncthreads();
        if (w == 0) {
            int u = wsum[lane];
            #pragma unroll
            for (int o = 1; o < 32; o <<= 1) {
                int uu = __shfl_up_sync(0xffffffffu, u, o);
                if (lane >= o) u += uu;
            }
            wsum[lane] = u;
        }
        __syncthreads();

        int excl = carry + (w > 0 ? wsum[w - 1] : 0) + incl - d;
        if (idx < NN) {
            g_off[idx] = excl;
            g_cur[idx] = excl;
            g_inv[idx] = d > 0 ? (1.f / (float)d) : 0.f;
        }
        int total = wsum[31];
        __syncthreads();
        if (t == 0) sh_carry = carry + total;
        __syncthreads();
    }
    if (t == 0) g_off[NN] = EE;
}

__global__ void k_scatter(const int* __restrict__ src, const int* __restrict__ dst,
                          const int* __restrict__ erel) {
    int i = blockIdx.x * blockDim.x + threadIdx.x;
    if (i < EE) {
        int d = dst[i];
        int pos = atomicAdd(&g_cur[d], 1);
        g_csr[pos] = make_int2(src[i], erel[i]);
    }
}

// ---------------- gather (fp16 h): aggH[v]=mean h[src], aggR[v]=mean rel -------
__device__ __forceinline__ void acc_h4(float4& a, uint2 hw) {
    float2 lo = __half22float2(*reinterpret_cast<__half2*>(&hw.x));
    float2 hi = __half22float2(*reinterpret_cast<__half2*>(&hw.y));
    a.x += lo.x; a.y += lo.y; a.z += hi.x; a.w += hi.y;
}

__global__ __launch_bounds__(256) void k_gather(
    const __half* __restrict__ hin, const float* __restrict__ rel)
{
    __shared__ int2 stage[8][32];
    int w = threadIdx.x >> 5, lane = threadIdx.x & 31;
    int v = blockIdx.x * 8 + w;
    if (v >= NN) return;
    int2* st = stage[w];
    const uint2* hb = (const uint2*)hin;   // 4 halves per uint2, 32 per row

    int e = g_off[v], end = g_off[v + 1];
    float4 a0 = make_float4(0.f, 0.f, 0.f, 0.f), a1 = a0, a2 = a0, a3 = a0;
    float r0s = 0.f, r1s = 0.f, r2s = 0.f, r3s = 0.f;

    while (e < end) {
        int n = min(32, end - e);
        if (lane < n) st[lane] = g_csr[e + lane];
        __syncwarp();
        int j = 0;
        for (; j + 4 <= n; j += 4) {
            int2 p0 = st[j], p1 = st[j + 1], p2 = st[j + 2], p3 = st[j + 3];
            uint2 h0 = hb[(size_t)p0.x * 32 + lane];
            uint2 h1 = hb[(size_t)p1.x * 32 + lane];
            uint2 h2 = hb[(size_t)p2.x * 32 + lane];
            uint2 h3 = hb[(size_t)p3.x * 32 + lane];
            float q0 = rel[p0.y * RD + lane];
            float q1 = rel[p1.y * RD + lane];
            float q2 = rel[p2.y * RD + lane];
            float q3 = rel[p3.y * RD + lane];
            acc_h4(a0, h0); acc_h4(a1, h1); acc_h4(a2, h2); acc_h4(a3, h3);
            r0s += q0; r1s += q1; r2s += q2; r3s += q3;
        }
        for (; j < n; j++) {
            int2 p0 = st[j];
            uint2 h0 = hb[(size_t)p0.x * 32 + lane];
            acc_h4(a0, h0);
            r0s += rel[p0.y * RD + lane];
        }
        e += n;
        __syncwarp();
    }

    float iv = g_inv[v];
    float4 acc;
    acc.x = (a0.x + a1.x + a2.x + a3.x) * iv;
    acc.y = (a0.y + a1.y + a2.y + a3.y) * iv;
    acc.z = (a0.z + a1.z + a2.z + a3.z) * iv;
    acc.w = (a0.w + a1.w + a2.w + a3.w) * iv;
    uint2 outw;
    __half2 lo = __floats2half2_rn(acc.x, acc.y);
    __half2 hi = __floats2half2_rn(acc.z, acc.w);
    outw.x = *reinterpret_cast<unsigned*>(&lo);
    outw.y = *reinterpret_cast<unsigned*>(&hi);
    ((uint2*)g_aggH)[(size_t)v * 32 + lane] = outw;
    g_aggR[v * RD + lane] = __float2half((r0s + r1s + r2s + r3s) * iv);
}

// ---------------- fp16 mma machinery --------------------------------------------
extern __shared__ float smdyn[];

__device__ __forceinline__ unsigned ldh2(const float* p) {
    float2 f = *(const float2*)p;
    __half2 h = __float22half2_rn(f);
    return *(unsigned*)&h;
}
__device__ __forceinline__ unsigned packh2(float a, float b) {
    __half2 h = __floats2half2_rn(a, b);
    return *(unsigned*)&h;
}

#define MMA_H(CI, A0, A1, A2, A3, B0, B1)                                       \
    asm("mma.sync.aligned.m16n8k16.row.col.f32.f16.f16.f32 "                    \
        "{%0,%1,%2,%3},{%4,%5,%6,%7},{%8,%9},{%0,%1,%2,%3};"                    \
        : "+f"(c[(CI)]), "+f"(c[(CI)+1]), "+f"(c[(CI)+2]), "+f"(c[(CI)+3])      \
        : "r"(A0), "r"(A1), "r"(A2), "r"(A3), "r"(B0), "r"(B1));

#define MMA_ROW16H(BP)                                                          \
    _Pragma("unroll")                                                           \
    for (int nt = 0; nt < 16; nt++) {                                           \
        uint2 b = (BP)[nt * 32];                                                \
        MMA_H(nt * 4, a0, a1, a2, a3, b.x, b.y)                                 \
    }

// ---------------- input projection: h = relu([x, lemb[label]] @ W + b) ---------
// K = 160 -> 10 k-steps (8 from x, 2 from label emb); writes fp16 h
__global__ __launch_bounds__(512) void k_input(
    const float* __restrict__ x, const int* __restrict__ label,
    const float* __restrict__ lemb, const float* __restrict__ W,
    const float* __restrict__ b, __half* __restrict__ hout)
{
    float* bs = smdyn;                       // 128 floats
    uint2* Bp = (uint2*)(bs + DM);           // 10*512 uint2

    int tid = threadIdx.x;
    for (int idx = tid; idx < 10 * 512; idx += 512) {
        int kk = idx >> 9, r = idx & 511;
        int nt = r >> 5, ln = r & 31;
        int n = nt * 8 + (ln >> 2);
        int kb = kk * 16 + (ln & 3) * 2;
        unsigned r0 = packh2(W[kb * DM + n],       W[(kb + 1) * DM + n]);
        unsigned r1 = packh2(W[(kb + 8) * DM + n], W[(kb + 9) * DM + n]);
        Bp[idx] = make_uint2(r0, r1);
    }
    for (int i = tid; i < DM; i += 512) bs[i] = b[i];
    __syncthreads();

    int w = tid >> 5, lane = tid & 31, q = lane & 3, g = lane >> 2;
    const uint2* bpl = Bp + lane;

    for (int tb = blockIdx.x; tb < NT2; tb += gridDim.x) {
        int v0w = tb * 256 + w * 16;
        if (v0w >= NN) continue;
        int va = min(v0w + g, NN - 1);
        int vb = min(v0w + g + 8, NN - 1);
        int la = __ldg(&label[va]);
        int lb = __ldg(&label[vb]);

        float c[64];
        #pragma unroll
        for (int i = 0; i < 64; i++) c[i] = 0.f;

        #pragma unroll
        for (int kk = 0; kk < 8; kk++) {
            int kb = kk * 16 + q * 2;
            unsigned a0 = ldh2(x + (size_t)va * DM + kb);
            unsigned a1 = ldh2(x + (size_t)vb * DM + kb);
            unsigned a2 = ldh2(x + (size_t)va * DM + kb + 8);
            unsigned a3 = ldh2(x + (size_t)vb * DM + kb + 8);
            const uint2* bp = bpl + kk * 512;
            MMA_ROW16H(bp)
        }
        #pragma unroll
        for (int kk = 8; kk < 10; kk++) {
            int kb = kk * 16 + q * 2 - 128;
            unsigned a0 = ldh2(lemb + (size_t)la * RD + kb);
            unsigned a1 = ldh2(lemb + (size_t)lb * RD + kb);
            unsigned a2 = ldh2(lemb + (size_t)la * RD + kb + 8);
            unsigned a3 = ldh2(lemb + (size_t)lb * RD + kb + 8);
            const uint2* bp = bpl + kk * 512;
            MMA_ROW16H(bp)
        }

        // register epilogue: bias + relu, half2 stores
        int ra = v0w + g, rb = v0w + g + 8;
        #pragma unroll
        for (int nt = 0; nt < 16; nt++) {
            float2 bv = *(float2*)(bs + nt * 8 + 2 * q);
            if (ra < NN) {
                *(unsigned*)(hout + (size_t)ra * DM + nt * 8 + 2 * q) =
                    packh2(fmaxf(c[nt*4+0] + bv.x, 0.f), fmaxf(c[nt*4+1] + bv.y, 0.f));
            }
            if (rb < NN) {
                *(unsigned*)(hout + (size_t)rb * DM + nt * 8 + 2 * q) =
                    packh2(fmaxf(c[nt*4+2] + bv.x, 0.f), fmaxf(c[nt*4+3] + bv.y, 0.f));
            }
        }
    }
}

// ---------------- node pass: fp16 mma 3-GEMM + bias + relu + layernorm ---------
// K = 288 -> 18 k-steps (8 from h, 8 from aggH, 2 from aggR)
// Writes fp16 (hout_h) for layer 0, fp32 (hout_f) for the final layer.
__global__ __launch_bounds__(512) void k_node(
    const __half* __restrict__ hin,
    const float* __restrict__ Wself, const float* __restrict__ Wn,
    const float* __restrict__ Wr, const float* __restrict__ bias,
    const float* __restrict__ lng, const float* __restrict__ lnb,
    __half* __restrict__ hout_h, float* __restrict__ hout_f)
{
    float* bs  = smdyn;                      // 128
    float* gs  = bs + DM;                    // 128
    float* lbs = gs + DM;                    // 128
    uint2* Bp  = (uint2*)(lbs + DM);         // 18*512 uint2

    int tid = threadIdx.x;
    for (int idx = tid; idx < 18 * 512; idx += 512) {
        int kk = idx >> 9, r = idx & 511;
        int nt = r >> 5, ln = r & 31;
        int n = nt * 8 + (ln >> 2);
        int kb = kk * 16 + (ln & 3) * 2;
        float w00, w01, w10, w11;
        if (kb < 128) {
            w00 = Wself[kb * DM + n];       w01 = Wself[(kb + 1) * DM + n];
            w10 = Wself[(kb + 8) * DM + n]; w11 = Wself[(kb + 9) * DM + n];
        } else if (kb < 256) {
            int k2 = kb - 128;
            w00 = Wn[k2 * DM + n];          w01 = Wn[(k2 + 1) * DM + n];
            w10 = Wn[(k2 + 8) * DM + n];    w11 = Wn[(k2 + 9) * DM + n];
        } else {
            int k2 = kb - 256;
            w00 = Wr[k2 * DM + n];          w01 = Wr[(k2 + 1) * DM + n];
            w10 = Wr[(k2 + 8) * DM + n];    w11 = Wr[(k2 + 9) * DM + n];
        }
        Bp[idx] = make_uint2(packh2(w00, w01), packh2(w10, w11));
    }
    for (int i = tid; i < DM; i += 512) {
        bs[i] = bias[i]; gs[i] = lng[i]; lbs[i] = lnb[i];
    }
    __syncthreads();

    int w = tid >> 5, lane = tid & 31, q = lane & 3, g = lane >> 5 ? 0 : (lane >> 2);
    g = lane >> 2;   // (keep simple)
    const uint2* bpl = Bp + lane;

    for (int tb = blockIdx.x; tb < NT2; tb += gridDim.x) {
        int v0w = tb * 256 + w * 16;
        if (v0w >= NN) continue;
        int va = min(v0w + g, NN - 1);
        int vb = min(v0w + g + 8, NN - 1);

        float c[64];
        #pragma unroll
        for (int i = 0; i < 64; i++) c[i] = 0.f;

        #pragma unroll
        for (int kk = 0; kk < 8; kk++) {
            int kb = kk * 16 + q * 2;
            unsigned a0 = *(const unsigned*)(hin + (size_t)va * DM + kb);
            unsigned a1 = *(const unsigned*)(hin + (size_t)vb * DM + kb);
            unsigned a2 = *(const unsigned*)(hin + (size_t)va * DM + kb + 8);
            unsigned a3 = *(const unsigned*)(hin + (size_t)vb * DM + kb + 8);
            const uint2* bp = bpl + kk * 512;
            MMA_ROW16H(bp)
        }
        #pragma unroll
        for (int kk = 8; kk < 16; kk++) {
            int kb = kk * 16 + q * 2 - 128;
            unsigned a0 = *(const unsigned*)(g_aggH + (size_t)va * DM + kb);
            unsigned a1 = *(const unsigned*)(g_aggH + (size_t)vb * DM + kb);
            unsigned a2 = *(const unsigned*)(g_aggH + (size_t)va * DM + kb + 8);
            unsigned a3 = *(const unsigned*)(g_aggH + (size_t)vb * DM + kb + 8);
            const uint2* bp = bpl + kk * 512;
            MMA_ROW16H(bp)
        }
        #pragma unroll
        for (int kk = 16; kk < 18; kk++) {
            int kb = kk * 16 + q * 2 - 256;
            unsigned a0 = *(const unsigned*)(g_aggR + (size_t)va * RD + kb);
            unsigned a1 = *(const unsigned*)(g_aggR + (size_t)vb * RD + kb);
            unsigned a2 = *(const unsigned*)(g_aggR + (size_t)va * RD + kb + 8);
            unsigned a3 = *(const unsigned*)(g_aggR + (size_t)vb * RD + kb + 8);
            const uint2* bp = bpl + kk * 512;
            MMA_ROW16H(bp)
        }

        // register epilogue: bias + relu + LN (quad-shuffle stats) + store
        float s1a = 0.f, s2a = 0.f, s1b = 0.f, s2b = 0.f;
        #pragma unroll
        for (int nt = 0; nt < 16; nt++) {
            float2 bv = *(float2*)(bs + nt * 8 + 2 * q);
            float c0 = fmaxf(c[nt*4+0] + bv.x, 0.f);
            float c1 = fmaxf(c[nt*4+1] + bv.y, 0.f);
            float c2 = fmaxf(c[nt*4+2] + bv.x, 0.f);
            float c3 = fmaxf(c[nt*4+3] + bv.y, 0.f);
            c[nt*4+0] = c0; c[nt*4+1] = c1; c[nt*4+2] = c2; c[nt*4+3] = c3;
            s1a += c0 + c1; s2a += c0 * c0 + c1 * c1;
            s1b += c2 + c3; s2b += c2 * c2 + c3 * c3;
        }
        #pragma unroll
        for (int m = 1; m <= 2; m <<= 1) {
            s1a += __shfl_xor_sync(0xffffffffu, s1a, m);
            s2a += __shfl_xor_sync(0xffffffffu, s2a, m);
            s1b += __shfl_xor_sync(0xffffffffu, s1b, m);
            s2b += __shfl_xor_sync(0xffffffffu, s2b, m);
        }
        float mua = s1a * (1.f / 128.f);
        float rsa = rsqrtf(s2a * (1.f / 128.f) - mua * mua + LN_EPS);
        float mub = s1b * (1.f / 128.f);
        float rsb = rsqrtf(s2b * (1.f / 128.f) - mub * mub + LN_EPS);

        int ra = v0w + g, rb = v0w + g + 8;
        if (hout_f) {
            #pragma unroll
            for (int nt = 0; nt < 16; nt++) {
                float2 gv = *(float2*)(gs + nt * 8 + 2 * q);
                float2 lv = *(float2*)(lbs + nt * 8 + 2 * q);
                if (ra < NN) {
                    float2 o = make_float2((c[nt*4+0] - mua) * rsa * gv.x + lv.x,
                                           (c[nt*4+1] - mua) * rsa * gv.y + lv.y);
                    *(float2*)(hout_f + (size_t)ra * DM + nt * 8 + 2 * q) = o;
                }
                if (rb < NN) {
                    float2 o = make_float2((c[nt*4+2] - mub) * rsb * gv.x + lv.x,
                                           (c[nt*4+3] - mub) * rsb * gv.y + lv.y);
                    *(float2*)(hout_f + (size_t)rb * DM + nt * 8 + 2 * q) = o;
                }
            }
        } else {
            #pragma unroll
            for (int nt = 0; nt < 16; nt++) {
                float2 gv = *(float2*)(gs + nt * 8 + 2 * q);
                float2 lv = *(float2*)(lbs + nt * 8 + 2 * q);
                if (ra < NN) {
                    *(unsigned*)(hout_h + (size_t)ra * DM + nt * 8 + 2 * q) =
                        packh2((c[nt*4+0] - mua) * rsa * gv.x + lv.x,
                               (c[nt*4+1] - mua) * rsa * gv.y + lv.y);
                }
                if (rb < NN) {
                    *(unsigned*)(hout_h + (size_t)rb * DM + nt * 8 + 2 * q) =
                        packh2((c[nt*4+2] - mub) * rsb * gv.x + lv.x,
                               (c[nt*4+3] - mub) * rsb * gv.y + lv.y);
                }
            }
        }
    }
}

// ---------------- host launch ------------------------------------------------------
extern "C" void kernel_launch(void* const* d_in, const int* in_sizes, int n_in,
                              void* d_out, int out_size)
{
    const float* x      = (const float*)d_in[0];
    const int*   label  = (const int*)d_in[1];
    const int*   eidx   = (const int*)d_in[2];
    const int*   erel   = (const int*)d_in[3];
    const float* lemb   = (const float*)d_in[4];
    const float* Win    = (const float*)d_in[5];
    const float* bin    = (const float*)d_in[6];
    const float* relemb = (const float*)d_in[7];
    const float* Wn     = (const float*)d_in[8];
    const float* Wself  = (const float*)d_in[9];
    const float* bself  = (const float*)d_in[10];
    const float* Wr     = (const float*)d_in[11];
    const float* lng    = (const float*)d_in[12];
    const float* lnb    = (const float*)d_in[13];
    float* out = (float*)d_out;

    __half *p_hA, *p_hB;
    int *p_deg;
    cudaGetSymbolAddress((void**)&p_hA,  g_hA);
    cudaGetSymbolAddress((void**)&p_hB,  g_hB);
    cudaGetSymbolAddress((void**)&p_deg, g_deg);

    const int smemI = 512 + 10 * 512 * 8;          // 41472
    const int smemN = 1536 + 18 * 512 * 8;         // 75264
    cudaFuncSetAttribute(k_input, cudaFuncAttributeMaxDynamicSharedMemorySize, smemI);
    cudaFuncSetAttribute(k_node,  cudaFuncAttributeMaxDynamicSharedMemorySize, smemN);

    // CSR build
    cudaMemsetAsync(p_deg, 0, NN * sizeof(int));
    k_deg<<<(EE + 255) / 256, 256>>>(eidx + EE);
    k_scan<<<1, 1024>>>();
    k_scatter<<<(EE + 255) / 256, 256>>>(eidx, eidx + EE, erel);

    // input projection (fp16 mma -> fp16 h)
    k_input<<<148, 512, smemI>>>(x, label, lemb, Win, bin, p_hA);

    const __half* hin = p_hA;
    for (int l = 0; l < 2; l++) {
        k_gather<<<(NN + 7) / 8, 256>>>(hin, relemb + l * 1024 * RD);
        k_node<<<148, 512, smemN>>>(hin,
                                    Wself + l * DM * DM, Wn + l * DM * DM,
                                    Wr + l * RD * DM, bself + l * DM,
                                    lng + l * DM, lnb + l * DM,
                                    (l == 0) ? p_hB : (__half*)nullptr,
                                    (l == 0) ? (float*)nullptr : out);
        hin = p_hB;
    }
}

// round 14
// speedup vs baseline: 2.1987x; 1.0873x over previous
#include <cuda_runtime.h>
#include <cuda_fp16.h>

#define NN 50000
#define EE 800000
#define DM 128
#define RD 32
#define LN_EPS 1e-5f
#define NT2 ((NN + 255) / 256)   // 196 tiles of 256 nodes

// ---------------- scratch (fp16 intermediates) ---------------------------------
__device__ __half g_hA[NN * DM];     // h after input proj (layer-0 input)
__device__ __half g_hB[NN * DM];     // layer-0 output (layer-1 input)
__device__ __half g_aggH[NN * DM];
__device__ __half g_aggR[NN * RD];
__device__ float  g_inv[NN];
__device__ int    g_deg[NN];
__device__ int    g_off[NN + 1];
__device__ int    g_cur[NN];
__device__ int2   g_csr[EE];         // (src, rel) grouped by dst

// ---------------- CSR build ----------------------------------------------------
__global__ void k_deg(const int* __restrict__ dst) {
    int i = blockIdx.x * blockDim.x + threadIdx.x;
    if (i < EE) atomicAdd(&g_deg[dst[i]], 1);
}

__global__ __launch_bounds__(1024) void k_scan() {
    __shared__ int wsum[32];
    __shared__ int sh_carry;
    int t = threadIdx.x, lane = t & 31, w = t >> 5;
    if (t == 0) sh_carry = 0;
    __syncthreads();

    for (int base = 0; base < NN; base += 1024) {
        int idx = base + t;
        int d = (idx < NN) ? g_deg[idx] : 0;
        int carry = sh_carry;

        int incl = d;
        #pragma unroll
        for (int o = 1; o < 32; o <<= 1) {
            int u = __shfl_up_sync(0xffffffffu, incl, o);
            if (lane >= o) incl += u;
        }
        if (lane == 31) wsum[w] = incl;
        __syncthreads();
        if (w == 0) {
            int u = wsum[lane];
            #pragma unroll
            for (int o = 1; o < 32; o <<= 1) {
                int uu = __shfl_up_sync(0xffffffffu, u, o);
                if (lane >= o) u += uu;
            }
            wsum[lane] = u;
        }
        __syncthreads();

        int excl = carry + (w > 0 ? wsum[w - 1] : 0) + incl - d;
        if (idx < NN) {
            g_off[idx] = excl;
            g_cur[idx] = excl;
            g_inv[idx] = d > 0 ? (1.f / (float)d) : 0.f;
        }
        int total = wsum[31];
        __syncthreads();
        if (t == 0) sh_carry = carry + total;
        __syncthreads();
    }
    if (t == 0) g_off[NN] = EE;
}

__global__ void k_scatter(const int* __restrict__ src, const int* __restrict__ dst,
                          const int* __restrict__ erel) {
    int i = blockIdx.x * blockDim.x + threadIdx.x;
    if (i < EE) {
        int d = dst[i];
        int pos = atomicAdd(&g_cur[d], 1);
        g_csr[pos] = make_int2(src[i], erel[i]);
    }
}

// ---------------- gather (fp16 h): aggH[v]=mean h[src], aggR[v]=mean rel -------
__device__ __forceinline__ void acc_h4(float4& a, uint2 hw) {
    float2 lo = __half22float2(*reinterpret_cast<__half2*>(&hw.x));
    float2 hi = __half22float2(*reinterpret_cast<__half2*>(&hw.y));
    a.x += lo.x; a.y += lo.y; a.z += hi.x; a.w += hi.y;
}

__global__ __launch_bounds__(256) void k_gather(
    const __half* __restrict__ hin, const float* __restrict__ rel)
{
    __shared__ int2 stage[8][32];
    int w = threadIdx.x >> 5, lane = threadIdx.x & 31;
    int v = blockIdx.x * 8 + w;
    if (v >= NN) return;
    int2* st = stage[w];
    const uint2* hb = (const uint2*)hin;

    int e = g_off[v], end = g_off[v + 1];
    float4 a0 = make_float4(0.f, 0.f, 0.f, 0.f), a1 = a0, a2 = a0, a3 = a0;
    float r0s = 0.f, r1s = 0.f, r2s = 0.f, r3s = 0.f;

    while (e < end) {
        int n = min(32, end - e);
        if (lane < n) st[lane] = g_csr[e + lane];
        __syncwarp();
        int j = 0;
        for (; j + 4 <= n; j += 4) {
            int2 p0 = st[j], p1 = st[j + 1], p2 = st[j + 2], p3 = st[j + 3];
            uint2 h0 = hb[(size_t)p0.x * 32 + lane];
            uint2 h1 = hb[(size_t)p1.x * 32 + lane];
            uint2 h2 = hb[(size_t)p2.x * 32 + lane];
            uint2 h3 = hb[(size_t)p3.x * 32 + lane];
            float q0 = rel[p0.y * RD + lane];
            float q1 = rel[p1.y * RD + lane];
            float q2 = rel[p2.y * RD + lane];
            float q3 = rel[p3.y * RD + lane];
            acc_h4(a0, h0); acc_h4(a1, h1); acc_h4(a2, h2); acc_h4(a3, h3);
            r0s += q0; r1s += q1; r2s += q2; r3s += q3;
        }
        for (; j < n; j++) {
            int2 p0 = st[j];
            uint2 h0 = hb[(size_t)p0.x * 32 + lane];
            acc_h4(a0, h0);
            r0s += rel[p0.y * RD + lane];
        }
        e += n;
        __syncwarp();
    }

    float iv = g_inv[v];
    float4 acc;
    acc.x = (a0.x + a1.x + a2.x + a3.x) * iv;
    acc.y = (a0.y + a1.y + a2.y + a3.y) * iv;
    acc.z = (a0.z + a1.z + a2.z + a3.z) * iv;
    acc.w = (a0.w + a1.w + a2.w + a3.w) * iv;
    uint2 outw;
    __half2 lo = __floats2half2_rn(acc.x, acc.y);
    __half2 hi = __floats2half2_rn(acc.z, acc.w);
    outw.x = *reinterpret_cast<unsigned*>(&lo);
    outw.y = *reinterpret_cast<unsigned*>(&hi);
    ((uint2*)g_aggH)[(size_t)v * 32 + lane] = outw;
    g_aggR[v * RD + lane] = __float2half((r0s + r1s + r2s + r3s) * iv);
}

// ---------------- fp16 mma machinery --------------------------------------------
extern __shared__ float smdyn[];

__device__ __forceinline__ unsigned ldh2(const float* p) {
    float2 f = *(const float2*)p;
    __half2 h = __float22half2_rn(f);
    return *(unsigned*)&h;
}
__device__ __forceinline__ unsigned packh2(float a, float b) {
    __half2 h = __floats2half2_rn(a, b);
    return *(unsigned*)&h;
}

#define MMA_H(CI, A0, A1, A2, A3, B0, B1)                                       \
    asm("mma.sync.aligned.m16n8k16.row.col.f32.f16.f16.f32 "                    \
        "{%0,%1,%2,%3},{%4,%5,%6,%7},{%8,%9},{%0,%1,%2,%3};"                    \
        : "+f"(c[(CI)]), "+f"(c[(CI)+1]), "+f"(c[(CI)+2]), "+f"(c[(CI)+3])      \
        : "r"(A0), "r"(A1), "r"(A2), "r"(A3), "r"(B0), "r"(B1));

#define MMA_ROW16H(BP)                                                          \
    _Pragma("unroll")                                                           \
    for (int nt = 0; nt < 16; nt++) {                                           \
        uint2 b = (BP)[nt * 32];                                                \
        MMA_H(nt * 4, a0, a1, a2, a3, b.x, b.y)                                 \
    }

// ---------------- input projection: h = relu([x, lemb[label]] @ W + b) ---------
__global__ __launch_bounds__(512) void k_input(
    const float* __restrict__ x, const int* __restrict__ label,
    const float* __restrict__ lemb, const float* __restrict__ W,
    const float* __restrict__ b, __half* __restrict__ hout)
{
    float* bs = smdyn;                       // 128 floats
    uint2* Bp = (uint2*)(bs + DM);           // 10*512 uint2

    int tid = threadIdx.x;
    for (int idx = tid; idx < 10 * 512; idx += 512) {
        int kk = idx >> 9, r = idx & 511;
        int nt = r >> 5, ln = r & 31;
        int n = nt * 8 + (ln >> 2);
        int kb = kk * 16 + (ln & 3) * 2;
        unsigned r0 = packh2(W[kb * DM + n],       W[(kb + 1) * DM + n]);
        unsigned r1 = packh2(W[(kb + 8) * DM + n], W[(kb + 9) * DM + n]);
        Bp[idx] = make_uint2(r0, r1);
    }
    for (int i = tid; i < DM; i += 512) bs[i] = b[i];
    __syncthreads();

    int w = tid >> 5, lane = tid & 31, q = lane & 3, g = lane >> 2;
    const uint2* bpl = Bp + lane;

    for (int tb = blockIdx.x; tb < NT2; tb += gridDim.x) {
        int v0w = tb * 256 + w * 16;
        if (v0w >= NN) continue;
        int va = min(v0w + g, NN - 1);
        int vb = min(v0w + g + 8, NN - 1);
        int la = __ldg(&label[va]);
        int lb = __ldg(&label[vb]);

        float c[64];
        #pragma unroll
        for (int i = 0; i < 64; i++) c[i] = 0.f;

        #pragma unroll
        for (int kk = 0; kk < 8; kk++) {
            int kb = kk * 16 + q * 2;
            unsigned a0 = ldh2(x + (size_t)va * DM + kb);
            unsigned a1 = ldh2(x + (size_t)vb * DM + kb);
            unsigned a2 = ldh2(x + (size_t)va * DM + kb + 8);
            unsigned a3 = ldh2(x + (size_t)vb * DM + kb + 8);
            const uint2* bp = bpl + kk * 512;
            MMA_ROW16H(bp)
        }
        #pragma unroll
        for (int kk = 8; kk < 10; kk++) {
            int kb = kk * 16 + q * 2 - 128;
            unsigned a0 = ldh2(lemb + (size_t)la * RD + kb);
            unsigned a1 = ldh2(lemb + (size_t)lb * RD + kb);
            unsigned a2 = ldh2(lemb + (size_t)la * RD + kb + 8);
            unsigned a3 = ldh2(lemb + (size_t)lb * RD + kb + 8);
            const uint2* bp = bpl + kk * 512;
            MMA_ROW16H(bp)
        }

        int ra = v0w + g, rb = v0w + g + 8;
        #pragma unroll
        for (int nt = 0; nt < 16; nt++) {
            float2 bv = *(float2*)(bs + nt * 8 + 2 * q);
            if (ra < NN) {
                *(unsigned*)(hout + (size_t)ra * DM + nt * 8 + 2 * q) =
                    packh2(fmaxf(c[nt*4+0] + bv.x, 0.f), fmaxf(c[nt*4+1] + bv.y, 0.f));
            }
            if (rb < NN) {
                *(unsigned*)(hout + (size_t)rb * DM + nt * 8 + 2 * q) =
                    packh2(fmaxf(c[nt*4+2] + bv.x, 0.f), fmaxf(c[nt*4+3] + bv.y, 0.f));
            }
        }
    }
}

// ---------------- node pass: fp16 mma 3-GEMM + bias + relu + layernorm ---------
__global__ __launch_bounds__(512) void k_node(
    const __half* __restrict__ hin,
    const float* __restrict__ Wself, const float* __restrict__ Wn,
    const float* __restrict__ Wr, const float* __restrict__ bias,
    const float* __restrict__ lng, const float* __restrict__ lnb,
    __half* __restrict__ hout_h, float* __restrict__ hout_f)
{
    float* bs  = smdyn;                      // 128
    float* gs  = bs + DM;                    // 128
    float* lbs = gs + DM;                    // 128
    uint2* Bp  = (uint2*)(lbs + DM);         // 18*512 uint2

    int tid = threadIdx.x;
    for (int idx = tid; idx < 18 * 512; idx += 512) {
        int kk = idx >> 9, r = idx & 511;
        int nt = r >> 5, ln = r & 31;
        int n = nt * 8 + (ln >> 2);
        int kb = kk * 16 + (ln & 3) * 2;
        float w00, w01, w10, w11;
        if (kb < 128) {
            w00 = Wself[kb * DM + n];       w01 = Wself[(kb + 1) * DM + n];
            w10 = Wself[(kb + 8) * DM + n]; w11 = Wself[(kb + 9) * DM + n];
        } else if (kb < 256) {
            int k2 = kb - 128;
            w00 = Wn[k2 * DM + n];          w01 = Wn[(k2 + 1) * DM + n];
            w10 = Wn[(k2 + 8) * DM + n];    w11 = Wn[(k2 + 9) * DM + n];
        } else {
            int k2 = kb - 256;
            w00 = Wr[k2 * DM + n];          w01 = Wr[(k2 + 1) * DM + n];
            w10 = Wr[(k2 + 8) * DM + n];    w11 = Wr[(k2 + 9) * DM + n];
        }
        Bp[idx] = make_uint2(packh2(w00, w01), packh2(w10, w11));
    }
    for (int i = tid; i < DM; i += 512) {
        bs[i] = bias[i]; gs[i] = lng[i]; lbs[i] = lnb[i];
    }
    __syncthreads();

    int w = tid >> 5, lane = tid & 31, q = lane & 3, g = lane >> 2;
    const uint2* bpl = Bp + lane;

    for (int tb = blockIdx.x; tb < NT2; tb += gridDim.x) {
        int v0w = tb * 256 + w * 16;
        if (v0w >= NN) continue;
        int va = min(v0w + g, NN - 1);
        int vb = min(v0w + g + 8, NN - 1);

        float c[64];
        #pragma unroll
        for (int i = 0; i < 64; i++) c[i] = 0.f;

        #pragma unroll
        for (int kk = 0; kk < 8; kk++) {
            int kb = kk * 16 + q * 2;
            unsigned a0 = *(const unsigned*)(hin + (size_t)va * DM + kb);
            unsigned a1 = *(const unsigned*)(hin + (size_t)vb * DM + kb);
            unsigned a2 = *(const unsigned*)(hin + (size_t)va * DM + kb + 8);
            unsigned a3 = *(const unsigned*)(hin + (size_t)vb * DM + kb + 8);
            const uint2* bp = bpl + kk * 512;
            MMA_ROW16H(bp)
        }
        #pragma unroll
        for (int kk = 8; kk < 16; kk++) {
            int kb = kk * 16 + q * 2 - 128;
            unsigned a0 = *(const unsigned*)(g_aggH + (size_t)va * DM + kb);
            unsigned a1 = *(const unsigned*)(g_aggH + (size_t)vb * DM + kb);
            unsigned a2 = *(const unsigned*)(g_aggH + (size_t)va * DM + kb + 8);
            unsigned a3 = *(const unsigned*)(g_aggH + (size_t)vb * DM + kb + 8);
            const uint2* bp = bpl + kk * 512;
            MMA_ROW16H(bp)
        }
        #pragma unroll
        for (int kk = 16; kk < 18; kk++) {
            int kb = kk * 16 + q * 2 - 256;
            unsigned a0 = *(const unsigned*)(g_aggR + (size_t)va * RD + kb);
            unsigned a1 = *(const unsigned*)(g_aggR + (size_t)vb * RD + kb);
            unsigned a2 = *(const unsigned*)(g_aggR + (size_t)va * RD + kb + 8);
            unsigned a3 = *(const unsigned*)(g_aggR + (size_t)vb * RD + kb + 8);
            const uint2* bp = bpl + kk * 512;
            MMA_ROW16H(bp)
        }

        float s1a = 0.f, s2a = 0.f, s1b = 0.f, s2b = 0.f;
        #pragma unroll
        for (int nt = 0; nt < 16; nt++) {
            float2 bv = *(float2*)(bs + nt * 8 + 2 * q);
            float c0 = fmaxf(c[nt*4+0] + bv.x, 0.f);
            float c1 = fmaxf(c[nt*4+1] + bv.y, 0.f);
            float c2 = fmaxf(c[nt*4+2] + bv.x, 0.f);
            float c3 = fmaxf(c[nt*4+3] + bv.y, 0.f);
            c[nt*4+0] = c0; c[nt*4+1] = c1; c[nt*4+2] = c2; c[nt*4+3] = c3;
            s1a += c0 + c1; s2a += c0 * c0 + c1 * c1;
            s1b += c2 + c3; s2b += c2 * c2 + c3 * c3;
        }
        #pragma unroll
        for (int m = 1; m <= 2; m <<= 1) {
            s1a += __shfl_xor_sync(0xffffffffu, s1a, m);
            s2a += __shfl_xor_sync(0xffffffffu, s2a, m);
            s1b += __shfl_xor_sync(0xffffffffu, s1b, m);
            s2b += __shfl_xor_sync(0xffffffffu, s2b, m);
        }
        float mua = s1a * (1.f / 128.f);
        float rsa = rsqrtf(s2a * (1.f / 128.f) - mua * mua + LN_EPS);
        float mub = s1b * (1.f / 128.f);
        float rsb = rsqrtf(s2b * (1.f / 128.f) - mub * mub + LN_EPS);

        int ra = v0w + g, rb = v0w + g + 8;
        if (hout_f) {
            #pragma unroll
            for (int nt = 0; nt < 16; nt++) {
                float2 gv = *(float2*)(gs + nt * 8 + 2 * q);
                float2 lv = *(float2*)(lbs + nt * 8 + 2 * q);
                if (ra < NN) {
                    float2 o = make_float2((c[nt*4+0] - mua) * rsa * gv.x + lv.x,
                                           (c[nt*4+1] - mua) * rsa * gv.y + lv.y);
                    *(float2*)(hout_f + (size_t)ra * DM + nt * 8 + 2 * q) = o;
                }
                if (rb < NN) {
                    float2 o = make_float2((c[nt*4+2] - mub) * rsb * gv.x + lv.x,
                                           (c[nt*4+3] - mub) * rsb * gv.y + lv.y);
                    *(float2*)(hout_f + (size_t)rb * DM + nt * 8 + 2 * q) = o;
                }
            }
        } else {
            #pragma unroll
            for (int nt = 0; nt < 16; nt++) {
                float2 gv = *(float2*)(gs + nt * 8 + 2 * q);
                float2 lv = *(float2*)(lbs + nt * 8 + 2 * q);
                if (ra < NN) {
                    *(unsigned*)(hout_h + (size_t)ra * DM + nt * 8 + 2 * q) =
                        packh2((c[nt*4+0] - mua) * rsa * gv.x + lv.x,
                               (c[nt*4+1] - mua) * rsa * gv.y + lv.y);
                }
                if (rb < NN) {
                    *(unsigned*)(hout_h + (size_t)rb * DM + nt * 8 + 2 * q) =
                        packh2((c[nt*4+2] - mub) * rsb * gv.x + lv.x,
                               (c[nt*4+3] - mub) * rsb * gv.y + lv.y);
                }
            }
        }
    }
}

// ---------------- host launch ------------------------------------------------------
extern "C" void kernel_launch(void* const* d_in, const int* in_sizes, int n_in,
                              void* d_out, int out_size)
{
    const float* x      = (const float*)d_in[0];
    const int*   label  = (const int*)d_in[1];
    const int*   eidx   = (const int*)d_in[2];
    const int*   erel   = (const int*)d_in[3];
    const float* lemb   = (const float*)d_in[4];
    const float* Win    = (const float*)d_in[5];
    const float* bin    = (const float*)d_in[6];
    const float* relemb = (const float*)d_in[7];
    const float* Wn     = (const float*)d_in[8];
    const float* Wself  = (const float*)d_in[9];
    const float* bself  = (const float*)d_in[10];
    const float* Wr     = (const float*)d_in[11];
    const float* lng    = (const float*)d_in[12];
    const float* lnb    = (const float*)d_in[13];
    float* out = (float*)d_out;

    __half *p_hA, *p_hB;
    int *p_deg;
    cudaGetSymbolAddress((void**)&p_hA,  g_hA);
    cudaGetSymbolAddress((void**)&p_hB,  g_hB);
    cudaGetSymbolAddress((void**)&p_deg, g_deg);

    const int smemI = 512 + 10 * 512 * 8;          // 41472
    const int smemN = 1536 + 18 * 512 * 8;         // 75264
    cudaFuncSetAttribute(k_input, cudaFuncAttributeMaxDynamicSharedMemorySize, smemI);
    cudaFuncSetAttribute(k_node,  cudaFuncAttributeMaxDynamicSharedMemorySize, smemN);

    // fork-join: k_input on side stream overlaps the CSR build on stream 0.
    cudaStream_t s2;
    cudaEvent_t evFork, evJoin;
    cudaStreamCreateWithFlags(&s2, cudaStreamNonBlocking);
    cudaEventCreateWithFlags(&evFork, cudaEventDisableTiming);
    cudaEventCreateWithFlags(&evJoin, cudaEventDisableTiming);

    cudaEventRecord(evFork, 0);
    cudaStreamWaitEvent(s2, evFork, 0);

    // side stream: input projection (independent of CSR)
    k_input<<<148, 512, smemI, s2>>>(x, label, lemb, Win, bin, p_hA);
    cudaEventRecord(evJoin, s2);

    // stream 0: CSR build
    cudaMemsetAsync(p_deg, 0, NN * sizeof(int));
    k_deg<<<(EE + 255) / 256, 256>>>(eidx + EE);
    k_scan<<<1, 1024>>>();
    k_scatter<<<(EE + 255) / 256, 256>>>(eidx, eidx + EE, erel);

    // join: gather needs both CSR and h
    cudaStreamWaitEvent(0, evJoin, 0);

    const __half* hin = p_hA;
    for (int l = 0; l < 2; l++) {
        k_gather<<<(NN + 7) / 8, 256>>>(hin, relemb + l * 1024 * RD);
        k_node<<<148, 512, smemN>>>(hin,
                                    Wself + l * DM * DM, Wn + l * DM * DM,
                                    Wr + l * RD * DM, bself + l * DM,
                                    lng + l * DM, lnb + l * DM,
                                    (l == 0) ? p_hB : (__half*)nullptr,
                                    (l == 0) ? (float*)nullptr : out);
        hin = p_hB;
    }

    cudaEventDestroy(evFork);
    cudaEventDestroy(evJoin);
    cudaStreamDestroy(s2);
}